// round 2
// baseline (speedup 1.0000x reference)
#include <cuda_runtime.h>
#include <math.h>

#define NB    64     // B*N batches
#define NODES 512
#define FDIM  256
#define ALPHA 0.2f
#define MASK_VAL -9000000000000000.0f

// Scratch (device globals: allocation-free per harness rules)
__device__ float g_Wh[NB * NODES * FDIM];     // 33.5 MB
__device__ float g_att[NB * NODES * NODES];   // 67 MB
__device__ float g_src[NB * NODES];
__device__ float g_dst[NB * NODES];

// ---------------------------------------------------------------------------
// Tiled SGEMM: C[bz] = A[bz] @ B[bz], row-major, M=512, N=256, K template.
// Block tile 64x64, BK=16, 256 threads, 4x4 per thread.
// ---------------------------------------------------------------------------
template <int K, bool ELU>
__global__ __launch_bounds__(256) void gemm_tile(
    const float* __restrict__ A, const float* __restrict__ B, float* __restrict__ C,
    int aStride, int bStride, int cStride)
{
    const int N = FDIM;  // 256
    __shared__ float As[64][17];   // padded to dodge bank conflicts
    __shared__ float Bs[16][64];

    const int bz = blockIdx.z;
    const float* Ab = A + (long)bz * aStride;
    const float* Bb = B + (long)bz * bStride;
    float* Cb = C + (long)bz * cStride;

    const int m0 = blockIdx.y * 64;
    const int n0 = blockIdx.x * 64;
    const int t  = threadIdx.x;
    const int tr = (t / 16) * 4;
    const int tc = (t % 16) * 4;

    float acc[4][4] = {};

    for (int k0 = 0; k0 < K; k0 += 16) {
        // Load A tile: 64x16 floats, one float4 per thread
        {
            int li = t * 4;
            int r = li >> 4, c = li & 15;
            float4 v = *reinterpret_cast<const float4*>(Ab + (long)(m0 + r) * K + k0 + c);
            As[r][c + 0] = v.x; As[r][c + 1] = v.y;
            As[r][c + 2] = v.z; As[r][c + 3] = v.w;
        }
        // Load B tile: 16x64 floats, one float4 per thread
        {
            int li = t * 4;
            int r = li >> 6, c = li & 63;
            float4 v = *reinterpret_cast<const float4*>(Bb + (long)(k0 + r) * N + n0 + c);
            *reinterpret_cast<float4*>(&Bs[r][c]) = v;
        }
        __syncthreads();

        #pragma unroll
        for (int kk = 0; kk < 16; kk++) {
            float ra[4], rb[4];
            #pragma unroll
            for (int i = 0; i < 4; i++) ra[i] = As[tr + i][kk];
            #pragma unroll
            for (int j = 0; j < 4; j++) rb[j] = Bs[kk][tc + j];
            #pragma unroll
            for (int i = 0; i < 4; i++)
                #pragma unroll
                for (int j = 0; j < 4; j++)
                    acc[i][j] = fmaf(ra[i], rb[j], acc[i][j]);
        }
        __syncthreads();
    }

    #pragma unroll
    for (int i = 0; i < 4; i++) {
        float4 v;
        float* p = &acc[i][0];
        if (ELU) {
            #pragma unroll
            for (int j = 0; j < 4; j++) p[j] = p[j] > 0.f ? p[j] : (expf(p[j]) - 1.f);
        }
        v.x = p[0]; v.y = p[1]; v.z = p[2]; v.w = p[3];
        *reinterpret_cast<float4*>(Cb + (long)(m0 + tr + i) * N + n0 + tc) = v;
    }
}

// ---------------------------------------------------------------------------
// src/dst: per row r of g_Wh, src[r]=dot(Wh[r],a1), dst[r]=dot(Wh[r],a2).
// One warp per row, 8 rows per 256-thread block.
// ---------------------------------------------------------------------------
__global__ __launch_bounds__(256) void srcdst_kernel(const float* __restrict__ a)
{
    const int warp = threadIdx.x >> 5;
    const int lane = threadIdx.x & 31;
    const int rowG = blockIdx.x * 8 + warp;            // 0 .. NB*NODES-1
    const float* wh = g_Wh + (long)rowG * FDIM;

    float s1 = 0.f, s2 = 0.f;
    #pragma unroll
    for (int f = lane; f < FDIM; f += 32) {
        float v = wh[f];
        s1 = fmaf(v, a[f], s1);
        s2 = fmaf(v, a[FDIM + f], s2);
    }
    #pragma unroll
    for (int o = 16; o; o >>= 1) {
        s1 += __shfl_xor_sync(0xffffffffu, s1, o);
        s2 += __shfl_xor_sync(0xffffffffu, s2, o);
    }
    if (lane == 0) { g_src[rowG] = s1; g_dst[rowG] = s2; }
}

// ---------------------------------------------------------------------------
// Attention row softmax: one block (512 threads) per (bn, i).
// e_ij = leaky_relu(src_i + dst_j); masked by adj; softmax over j.
// ---------------------------------------------------------------------------
__global__ __launch_bounds__(512) void attn_kernel(const int* __restrict__ adj)
{
    const int i  = blockIdx.x;
    const int bn = blockIdx.y;
    const int j  = threadIdx.x;
    const int wid  = threadIdx.x >> 5;
    const int lane = threadIdx.x & 31;

    __shared__ float sred[16];
    __shared__ float sbc;

    const float si = g_src[bn * NODES + i];
    const float dj = g_dst[bn * NODES + j];
    float e = si + dj;
    e = e > 0.f ? e : ALPHA * e;
    e = (adj[i * NODES + j] > 0) ? e : MASK_VAL;

    // block max
    float mx = e;
    #pragma unroll
    for (int o = 16; o; o >>= 1) mx = fmaxf(mx, __shfl_xor_sync(0xffffffffu, mx, o));
    if (lane == 0) sred[wid] = mx;
    __syncthreads();
    if (threadIdx.x == 0) {
        float v = sred[0];
        #pragma unroll
        for (int k = 1; k < 16; k++) v = fmaxf(v, sred[k]);
        sbc = v;
    }
    __syncthreads();
    mx = sbc;

    const float p = expf(e - mx);

    // block sum
    float sm = p;
    #pragma unroll
    for (int o = 16; o; o >>= 1) sm += __shfl_xor_sync(0xffffffffu, sm, o);
    __syncthreads();              // protect sred reuse
    if (lane == 0) sred[wid] = sm;
    __syncthreads();
    if (threadIdx.x == 0) {
        float v = 0.f;
        #pragma unroll
        for (int k = 0; k < 16; k++) v += sred[k];
        sbc = v;
    }
    __syncthreads();

    g_att[((long)bn * NODES + i) * NODES + j] = p / sbc;
}

// ---------------------------------------------------------------------------
extern "C" void kernel_launch(void* const* d_in, const int* in_sizes, int n_in,
                              void* d_out, int out_size)
{
    const float* h   = (const float*)d_in[0];   // (8,8,512,256)
    const int*   adj = (const int*)d_in[1];     // (512,512)
    const float* W   = (const float*)d_in[2];   // (256,256)
    const float* a   = (const float*)d_in[3];   // (512,1)
    float* out = (float*)d_out;

    float *pWh, *pAtt;
    cudaGetSymbolAddress((void**)&pWh,  g_Wh);
    cudaGetSymbolAddress((void**)&pAtt, g_att);

    // 1) Wh = h @ W   (batched; B shared)
    {
        dim3 grid(FDIM / 64, NODES / 64, NB);
        gemm_tile<FDIM, false><<<grid, 256>>>(h, W, pWh,
                                              NODES * FDIM, 0, NODES * FDIM);
    }
    // 2) src/dst projections
    srcdst_kernel<<<NB * NODES / 8, 256>>>(a);

    // 3) masked softmax attention
    {
        dim3 grid(NODES, NB);
        attn_kernel<<<grid, 512>>>(adj);
    }
    // 4) h' = att @ Wh, ELU epilogue, straight into d_out
    {
        dim3 grid(FDIM / 64, NODES / 64, NB);
        gemm_tile<NODES, true><<<grid, 256>>>(pAtt, pWh, out,
                                              NODES * NODES, NODES * FDIM, NODES * FDIM);
    }
}

// round 4
// speedup vs baseline: 1.8838x; 1.8838x over previous
#include <cuda_runtime.h>
#include <cuda_bf16.h>
#include <cstdint>
#include <math.h>

#define NB    64
#define NODES 512
#define FDIM  256
#define ALPHA 0.2f
#define MASK_VAL -9000000000000000.0f

// ---------------- scratch (device globals; no allocation) ----------------
__device__ __nv_bfloat16 g_h_hi [NB * NODES * FDIM];
__device__ __nv_bfloat16 g_h_lo [NB * NODES * FDIM];
__device__ __nv_bfloat16 g_att_hi[NB * NODES * NODES];
__device__ __nv_bfloat16 g_att_lo[NB * NODES * NODES];
__device__ __nv_bfloat16 g_Wh_hi[NB * NODES * FDIM];
__device__ __nv_bfloat16 g_Wh_lo[NB * NODES * FDIM];
__device__ __nv_bfloat16 g_W_hi [FDIM * FDIM];
__device__ __nv_bfloat16 g_W_lo [FDIM * FDIM];
__device__ float g_src[NB * NODES];
__device__ float g_dst[NB * NODES];

// ---------------- helpers ----------------
__device__ __forceinline__ uint32_t smem_u32(const void* p) {
    uint32_t a;
    asm("{ .reg .u64 t; cvta.to.shared.u64 t, %1; cvt.u32.u64 %0, t; }" : "=r"(a) : "l"(p));
    return a;
}
__device__ __forceinline__ void cp16(uint32_t d, const void* g) {
    asm volatile("cp.async.cg.shared.global [%0], [%1], 16;" :: "r"(d), "l"(g));
}
#define CP_COMMIT() asm volatile("cp.async.commit_group;" ::: "memory")
#define CP_WAIT(n)  asm volatile("cp.async.wait_group %0;" :: "n"(n) : "memory")

#define LDSM4(r, addr)                                                       \
    asm volatile("ldmatrix.sync.aligned.m8n8.x4.shared.b16 {%0,%1,%2,%3}, [%4];" \
        : "=r"((r)[0]), "=r"((r)[1]), "=r"((r)[2]), "=r"((r)[3]) : "r"(addr))
#define LDSM4T(r0, r1, r2, r3, addr)                                         \
    asm volatile("ldmatrix.sync.aligned.m8n8.x4.trans.shared.b16 {%0,%1,%2,%3}, [%4];" \
        : "=r"(r0), "=r"(r1), "=r"(r2), "=r"(r3) : "r"(addr))

__device__ __forceinline__ void mma16816(float* d, const uint32_t* a, const uint32_t* b) {
    asm volatile(
        "mma.sync.aligned.m16n8k16.row.col.f32.bf16.bf16.f32 "
        "{%0,%1,%2,%3}, {%4,%5,%6,%7}, {%8,%9}, {%0,%1,%2,%3};"
        : "+f"(d[0]), "+f"(d[1]), "+f"(d[2]), "+f"(d[3])
        : "r"(a[0]), "r"(a[1]), "r"(a[2]), "r"(a[3]), "r"(b[0]), "r"(b[1]));
}

// A tile: [128 m][64 k] bf16 = 128B rows.  bits[6:4] ^= bits[9:7]
#define SWZA(x) ((x) ^ (((x) >> 3) & 0x70))
// B tile: [64 k][128 n] bf16 = 256B rows.  bits[6:4] ^= bits[10:8]
#define SWZB(x) ((x) ^ (((x) >> 4) & 0x70))

#define STAGE_SZ   32768          // A 16KB + B 16KB
#define SMEM_TOTAL (2 * STAGE_SZ) // 64 KB (epilogue reuses it for staging)

// FMA-only exp for x <= 0 (MUFU pipe is slow: rt_SMSP=8)
__device__ __forceinline__ float fast_exp(float x) {
    x = fmaxf(x, -80.0f);
    float n = rintf(x * 1.442695041f);
    float r = fmaf(n, -0.693359375f, x);
    r = fmaf(n, 2.12194440e-4f, r);
    float p = 1.9875691500E-4f;
    p = fmaf(p, r, 1.3981999507E-3f);
    p = fmaf(p, r, 8.3334519073E-3f);
    p = fmaf(p, r, 4.1665795894E-2f);
    p = fmaf(p, r, 1.6666665459E-1f);
    p = fmaf(p, r, 5.0000001201E-1f);
    float z = fmaf(p * r, r, r) + 1.0f;
    return z * __int_as_float(((int)n + 127) << 23);
}

// ============================================================================
// Warp-MMA GEMM: C[128x128 tile] = A[M][K] @ B[K][N], bf16 split 3-pass,
// fp32 accumulation.  A row-major (K contiguous), B row-major (N contiguous).
// EPI 0: write C as bf16 hi/lo (Wh).   EPI 1: ELU, write fp32 out.
// ============================================================================
template <int K, int EPI>
__global__ __launch_bounds__(256) void gemm_mma(
    const __nv_bfloat16* __restrict__ Ah, const __nv_bfloat16* __restrict__ Al,
    const __nv_bfloat16* __restrict__ Bh, const __nv_bfloat16* __restrict__ Bl,
    long aStride, long bStride,
    float* __restrict__ outp,
    __nv_bfloat16* __restrict__ Whh, __nv_bfloat16* __restrict__ Whl)
{
    extern __shared__ __align__(16) char smem[];
    const uint32_t sb = smem_u32(smem);
    const int tid  = threadIdx.x;
    const int lane = tid & 31;
    const int wid  = tid >> 5;
    const int wm   = wid >> 1;     // 0..3 (M direction, 32 rows each)
    const int wn   = wid & 1;      // 0..1 (N direction, 64 cols each)
    const int bz   = blockIdx.z;
    const int m0   = blockIdx.y * 128;
    const int n0   = blockIdx.x * 128;

    const __nv_bfloat16* Abh = Ah + (long)bz * aStride + (long)m0 * K;
    const __nv_bfloat16* Abl = Al + (long)bz * aStride + (long)m0 * K;
    const __nv_bfloat16* Bbh = Bh + (long)bz * bStride + n0;
    const __nv_bfloat16* Bbl = Bl + (long)bz * bStride + n0;

    constexpr int CPP = K / 64;   // chunks per pass
    constexpr int NC  = 3 * CPP;  // three split passes

    float acc[2][8][4];
    #pragma unroll
    for (int i = 0; i < 2; i++)
        #pragma unroll
        for (int j = 0; j < 8; j++)
            #pragma unroll
            for (int q = 0; q < 4; q++) acc[i][j][q] = 0.f;

    auto load_chunk = [&](int st, int c) {
        const int p  = c / CPP;
        const int k0 = (c % CPP) * 64;
        const __nv_bfloat16* A = (p < 2) ? Abh : Abl;
        const __nv_bfloat16* B = (p == 1) ? Bbl : Bbh;
        const uint32_t dA = sb + st * STAGE_SZ;
        const uint32_t dB = dA + 16384;
        #pragma unroll
        for (int i = 0; i < 4; i++) {              // A: 128 x 64 bf16
            int idx = tid + i * 256, r = idx >> 3, s = idx & 7;
            cp16(dA + SWZA(r * 128 + s * 16), A + (long)r * K + k0 + s * 8);
        }
        #pragma unroll
        for (int i = 0; i < 4; i++) {              // B: 64 x 128 bf16
            int idx = tid + i * 256, r = idx >> 4, s = idx & 15;
            cp16(dB + SWZB(r * 256 + s * 16), B + (long)(k0 + r) * FDIM + s * 8);
        }
        CP_COMMIT();
    };

    const int alr = lane & 15;
    const int alc = lane >> 4;

    load_chunk(0, 0);

    for (int c = 0; c < NC; ++c) {
        const int s = c & 1;
        if (c + 1 < NC) { load_chunk(s ^ 1, c + 1); CP_WAIT(1); }
        else            { CP_WAIT(0); }
        __syncthreads();

        const uint32_t sA = sb + s * STAGE_SZ;
        const uint32_t sB = sA + 16384;
        #pragma unroll
        for (int kk = 0; kk < 4; kk++) {
            uint32_t a[2][4];
            #pragma unroll
            for (int mt = 0; mt < 2; mt++)
                LDSM4(a[mt], sA + SWZA((wm * 32 + mt * 16 + alr) * 128 + kk * 32 + alc * 16));
            uint32_t b[8][2];
            #pragma unroll
            for (int np = 0; np < 4; np++) {
                uint32_t t0, t1, t2, t3;
                LDSM4T(t0, t1, t2, t3,
                       sB + SWZB((kk * 16 + alr) * 256 + (wn * 64 + np * 16 + alc * 8) * 2));
                b[2 * np][0] = t0; b[2 * np][1] = t1;
                b[2 * np + 1][0] = t2; b[2 * np + 1][1] = t3;
            }
            #pragma unroll
            for (int mt = 0; mt < 2; mt++)
                #pragma unroll
                for (int nt = 0; nt < 8; nt++)
                    mma16816(acc[mt][nt], a[mt], b[nt]);
        }
        __syncthreads();
    }

    const int g  = lane >> 2;
    const int t2 = (lane & 3) * 2;

    if (EPI == 0) {
        // stage bf16 hi (smem[0:32K)) and lo (smem[32K:64K)) tiles, then
        // fully coalesced 16B global writes.
        __nv_bfloat162* hiT = (__nv_bfloat162*)(smem);
        __nv_bfloat162* loT = (__nv_bfloat162*)(smem + 32768);
        #pragma unroll
        for (int mt = 0; mt < 2; mt++)
            #pragma unroll
            for (int nt = 0; nt < 8; nt++) {
                const int r  = wm * 32 + mt * 16 + g;
                const int cc = wn * 64 + nt * 8 + t2;
                float v0 = acc[mt][nt][0], v1 = acc[mt][nt][1];
                float v2 = acc[mt][nt][2], v3 = acc[mt][nt][3];
                __nv_bfloat162 h01, l01, h23, l23;
                h01.x = __float2bfloat16(v0); h01.y = __float2bfloat16(v1);
                l01.x = __float2bfloat16(v0 - __bfloat162float(h01.x));
                l01.y = __float2bfloat16(v1 - __bfloat162float(h01.y));
                h23.x = __float2bfloat16(v2); h23.y = __float2bfloat16(v3);
                l23.x = __float2bfloat16(v2 - __bfloat162float(h23.x));
                l23.y = __float2bfloat16(v3 - __bfloat162float(h23.y));
                hiT[(r * 128 + cc) >> 1]       = h01;
                loT[(r * 128 + cc) >> 1]       = l01;
                hiT[((r + 8) * 128 + cc) >> 1] = h23;
                loT[((r + 8) * 128 + cc) >> 1] = l23;
            }
        __syncthreads();
        #pragma unroll
        for (int i = 0; i < 8; i++) {
            int idx = tid + i * 256;        // 2048 x 16B per tile
            int r = idx >> 4, ch = idx & 15;
            long gofs = ((long)bz * NODES + m0 + r) * FDIM + n0 + ch * 8;
            *(uint4*)(Whh + gofs) = *(uint4*)(smem + r * 256 + ch * 16);
            *(uint4*)(Whl + gofs) = *(uint4*)(smem + 32768 + r * 256 + ch * 16);
        }
    } else {
        #pragma unroll
        for (int mt = 0; mt < 2; mt++)
            #pragma unroll
            for (int nt = 0; nt < 8; nt++) {
                const long base = ((long)bz * NODES + m0 + wm * 32 + mt * 16) * FDIM
                                + n0 + wn * 64 + nt * 8 + t2;
                float v0 = acc[mt][nt][0], v1 = acc[mt][nt][1];
                float v2 = acc[mt][nt][2], v3 = acc[mt][nt][3];
                float2 r01, r23;
                r01.x = v0 > 0.f ? v0 : fast_exp(v0) - 1.f;
                r01.y = v1 > 0.f ? v1 : fast_exp(v1) - 1.f;
                r23.x = v2 > 0.f ? v2 : fast_exp(v2) - 1.f;
                r23.y = v3 > 0.f ? v3 : fast_exp(v3) - 1.f;
                *(float2*)(outp + base + (long)g * FDIM)       = r01;
                *(float2*)(outp + base + (long)(g + 8) * FDIM) = r23;
            }
    }
}

// ============================================================================
// fp32 -> bf16 hi/lo split (elementwise, float4 granularity)
// ============================================================================
__global__ __launch_bounds__(256) void conv_split(const float4* __restrict__ in4,
                                                  __nv_bfloat16* __restrict__ hh,
                                                  __nv_bfloat16* __restrict__ hl)
{
    long i = (long)blockIdx.x * 256 + threadIdx.x;
    float4 v = in4[i];
    __nv_bfloat162 h0, h1, l0, l1;
    h0.x = __float2bfloat16(v.x); h0.y = __float2bfloat16(v.y);
    h1.x = __float2bfloat16(v.z); h1.y = __float2bfloat16(v.w);
    l0.x = __float2bfloat16(v.x - __bfloat162float(h0.x));
    l0.y = __float2bfloat16(v.y - __bfloat162float(h0.y));
    l1.x = __float2bfloat16(v.z - __bfloat162float(h1.x));
    l1.y = __float2bfloat16(v.w - __bfloat162float(h1.y));
    ((__nv_bfloat162*)hh)[2 * i] = h0; ((__nv_bfloat162*)hh)[2 * i + 1] = h1;
    ((__nv_bfloat162*)hl)[2 * i] = l0; ((__nv_bfloat162*)hl)[2 * i + 1] = l1;
}

// ============================================================================
// src/dst dots from reconstructed Wh (hi+lo).  One warp per node row.
// ============================================================================
__global__ __launch_bounds__(256) void srcdst_kernel(
    const __nv_bfloat16* __restrict__ Whh, const __nv_bfloat16* __restrict__ Whl,
    const float* __restrict__ a, float* __restrict__ srcv, float* __restrict__ dstv)
{
    const int warp = threadIdx.x >> 5;
    const int lane = threadIdx.x & 31;
    const long rowG = (long)blockIdx.x * 8 + warp;
    const __nv_bfloat162* wh2 = (const __nv_bfloat162*)(Whh + rowG * FDIM);
    const __nv_bfloat162* wl2 = (const __nv_bfloat162*)(Whl + rowG * FDIM);

    float s1 = 0.f, s2 = 0.f;
    #pragma unroll
    for (int it = 0; it < 4; it++) {
        int p = it * 32 + lane;                 // bf162 index, covers 128 pairs
        __nv_bfloat162 h2 = wh2[p], l2 = wl2[p];
        float v0 = __bfloat162float(h2.x) + __bfloat162float(l2.x);
        float v1 = __bfloat162float(h2.y) + __bfloat162float(l2.y);
        int f = p * 2;
        s1 = fmaf(v0, a[f], s1);     s1 = fmaf(v1, a[f + 1], s1);
        s2 = fmaf(v0, a[FDIM + f], s2); s2 = fmaf(v1, a[FDIM + f + 1], s2);
    }
    #pragma unroll
    for (int o = 16; o; o >>= 1) {
        s1 += __shfl_xor_sync(0xffffffffu, s1, o);
        s2 += __shfl_xor_sync(0xffffffffu, s2, o);
    }
    if (lane == 0) { srcv[rowG] = s1; dstv[rowG] = s2; }
}

// ============================================================================
// masked softmax attention -> bf16 hi/lo
// ============================================================================
__global__ __launch_bounds__(512) void attn_kernel(const int* __restrict__ adj,
                                                   const float* __restrict__ srcv,
                                                   const float* __restrict__ dstv,
                                                   __nv_bfloat16* __restrict__ att_h,
                                                   __nv_bfloat16* __restrict__ att_l)
{
    const int i  = blockIdx.x;
    const int bn = blockIdx.y;
    const int j  = threadIdx.x;
    const int w    = threadIdx.x >> 5;
    const int lane = threadIdx.x & 31;

    __shared__ float sred[16];
    __shared__ float sbc;

    const float si = srcv[bn * NODES + i];
    const float dj = dstv[bn * NODES + j];
    const int adjv = adj[i * NODES + j];
    float e = si + dj;
    e = e > 0.f ? e : ALPHA * e;
    e = (adjv > 0) ? e : MASK_VAL;

    float mx = e;
    #pragma unroll
    for (int o = 16; o; o >>= 1) mx = fmaxf(mx, __shfl_xor_sync(0xffffffffu, mx, o));
    if (lane == 0) sred[w] = mx;
    __syncthreads();
    if (threadIdx.x == 0) {
        float v = sred[0];
        #pragma unroll
        for (int k = 1; k < 16; k++) v = fmaxf(v, sred[k]);
        sbc = v;
    }
    __syncthreads();
    mx = sbc;

    const float p = (adjv > 0) ? fast_exp(e - mx) : 0.f;

    float sm = p;
    #pragma unroll
    for (int o = 16; o; o >>= 1) sm += __shfl_xor_sync(0xffffffffu, sm, o);
    __syncthreads();
    if (lane == 0) sred[w] = sm;
    __syncthreads();
    if (threadIdx.x == 0) {
        float v = 0.f;
        #pragma unroll
        for (int k = 0; k < 16; k++) v += sred[k];
        sbc = v;
    }
    __syncthreads();

    const float val = p / sbc;
    __nv_bfloat16 hi = __float2bfloat16(val);
    __nv_bfloat16 lo = __float2bfloat16(val - __bfloat162float(hi));
    const long idx = ((long)bn * NODES + i) * NODES + j;
    att_h[idx] = hi;
    att_l[idx] = lo;
}

// ============================================================================
extern "C" void kernel_launch(void* const* d_in, const int* in_sizes, int n_in,
                              void* d_out, int out_size)
{
    const float* h   = (const float*)d_in[0];
    const int*   adj = (const int*)d_in[1];
    const float* W   = (const float*)d_in[2];
    const float* a   = (const float*)d_in[3];
    float* out = (float*)d_out;

    __nv_bfloat16 *hh, *hl, *ath, *atl, *wh, *wl, *whh, *whl;
    float *srcp, *dstp;
    cudaGetSymbolAddress((void**)&hh,  g_h_hi);
    cudaGetSymbolAddress((void**)&hl,  g_h_lo);
    cudaGetSymbolAddress((void**)&ath, g_att_hi);
    cudaGetSymbolAddress((void**)&atl, g_att_lo);
    cudaGetSymbolAddress((void**)&wh,  g_W_hi);
    cudaGetSymbolAddress((void**)&wl,  g_W_lo);
    cudaGetSymbolAddress((void**)&whh, g_Wh_hi);
    cudaGetSymbolAddress((void**)&whl, g_Wh_lo);
    cudaGetSymbolAddress((void**)&srcp, g_src);
    cudaGetSymbolAddress((void**)&dstp, g_dst);

    cudaFuncSetAttribute(gemm_mma<FDIM, 0>,  cudaFuncAttributeMaxDynamicSharedMemorySize, SMEM_TOTAL);
    cudaFuncSetAttribute(gemm_mma<NODES, 1>, cudaFuncAttributeMaxDynamicSharedMemorySize, SMEM_TOTAL);

    // 1) fp32 -> bf16 hi/lo
    conv_split<<<(NB * NODES * FDIM) / (4 * 256), 256>>>((const float4*)h, hh, hl);
    conv_split<<<(FDIM * FDIM) / (4 * 256), 256>>>((const float4*)W, wh, wl);

    // 2) GEMM1: Wh = h @ W  (HMMA split bf16) -> Wh hi/lo
    {
        dim3 grid(FDIM / 128, NODES / 128, NB);
        gemm_mma<FDIM, 0><<<grid, 256, SMEM_TOTAL>>>(
            hh, hl, wh, wl,
            (long)NODES * FDIM, 0L,
            nullptr, whh, whl);
    }

    // 3) src/dst projections
    srcdst_kernel<<<NB * NODES / 8, 256>>>(whh, whl, a, srcp, dstp);

    // 4) masked softmax -> attention hi/lo
    {
        dim3 grid(NODES, NB);
        attn_kernel<<<grid, 512>>>(adj, srcp, dstp, ath, atl);
    }

    // 5) GEMM2: out = elu(att @ Wh)  (HMMA split bf16)
    {
        dim3 grid(FDIM / 128, NODES / 128, NB);
        gemm_mma<NODES, 1><<<grid, 256, SMEM_TOTAL>>>(
            ath, atl, whh, whl,
            (long)NODES * NODES, (long)NODES * FDIM,
            out, nullptr, nullptr);
    }
}

// round 5
// speedup vs baseline: 2.0084x; 1.0661x over previous
#include <cuda_runtime.h>
#include <cuda_fp16.h>
#include <cstdint>
#include <math.h>

#define NB    64
#define NODES 512
#define FDIM  256
#define ALPHA 0.2f
#define MASK_VAL -9000000000000000.0f

// ---------------- scratch ----------------
__device__ __half g_h_hi [NB * NODES * FDIM];
__device__ __half g_h_lo [NB * NODES * FDIM];
__device__ __half g_att  [NB * NODES * NODES];
__device__ __half g_Wh_hi[NB * NODES * FDIM];
__device__ __half g_Wh_lo[NB * NODES * FDIM];
__device__ __half g_W_hi [FDIM * FDIM];
__device__ __half g_W_lo [FDIM * FDIM];
__device__ float  g_srcp[2 * NB * NODES];   // per n-half partials
__device__ float  g_dstp[2 * NB * NODES];

// ---------------- helpers ----------------
__device__ __forceinline__ uint32_t smem_u32(const void* p) {
    uint32_t a;
    asm("{ .reg .u64 t; cvta.to.shared.u64 t, %1; cvt.u32.u64 %0, t; }" : "=r"(a) : "l"(p));
    return a;
}
__device__ __forceinline__ void cp16(uint32_t d, const void* g) {
    asm volatile("cp.async.cg.shared.global [%0], [%1], 16;" :: "r"(d), "l"(g));
}
#define CP_COMMIT() asm volatile("cp.async.commit_group;" ::: "memory")
#define CP_WAIT(n)  asm volatile("cp.async.wait_group %0;" :: "n"(n) : "memory")

#define LDSM4(r, addr)                                                       \
    asm volatile("ldmatrix.sync.aligned.m8n8.x4.shared.b16 {%0,%1,%2,%3}, [%4];" \
        : "=r"((r)[0]), "=r"((r)[1]), "=r"((r)[2]), "=r"((r)[3]) : "r"(addr))
#define LDSM4T(r0, r1, r2, r3, addr)                                         \
    asm volatile("ldmatrix.sync.aligned.m8n8.x4.trans.shared.b16 {%0,%1,%2,%3}, [%4];" \
        : "=r"(r0), "=r"(r1), "=r"(r2), "=r"(r3) : "r"(addr))

__device__ __forceinline__ void mma16816(float* d, const uint32_t* a, const uint32_t* b) {
    asm volatile(
        "mma.sync.aligned.m16n8k16.row.col.f32.f16.f16.f32 "
        "{%0,%1,%2,%3}, {%4,%5,%6,%7}, {%8,%9}, {%0,%1,%2,%3};"
        : "+f"(d[0]), "+f"(d[1]), "+f"(d[2]), "+f"(d[3])
        : "r"(a[0]), "r"(a[1]), "r"(a[2]), "r"(a[3]), "r"(b[0]), "r"(b[1]));
}

// A tile: 128B rows.  B tile: 256B rows.
#define SWZA(x) ((x) ^ (((x) >> 3) & 0x70))
#define SWZB(x) ((x) ^ (((x) >> 4) & 0x70))

// FMA-only exp for x <= 0
__device__ __forceinline__ float fast_exp(float x) {
    x = fmaxf(x, -80.0f);
    float n = rintf(x * 1.442695041f);
    float r = fmaf(n, -0.693359375f, x);
    r = fmaf(n, 2.12194440e-4f, r);
    float p = 1.9875691500E-4f;
    p = fmaf(p, r, 1.3981999507E-3f);
    p = fmaf(p, r, 8.3334519073E-3f);
    p = fmaf(p, r, 4.1665795894E-2f);
    p = fmaf(p, r, 1.6666665459E-1f);
    p = fmaf(p, r, 5.0000001201E-1f);
    float z = fmaf(p * r, r, r) + 1.0f;
    return z * __int_as_float(((int)n + 127) << 23);
}

// ============================================================================
// GEMM1: Wh = h @ W, fp16 split 3-pass (Ah·Bh + Ah·Bl + Al·Bh).
// Epilogue: write Wh fp16 hi/lo + fused src/dst partial dots.
// grid (FDIM/128, NODES/128, NB), 256 threads.
// ============================================================================
#define G1_STAGE 32768
#define G1_SMEM  (2 * G1_STAGE)
__global__ __launch_bounds__(256) void gemm1_kernel(
    const __half* __restrict__ Ah, const __half* __restrict__ Al,
    const __half* __restrict__ Bh, const __half* __restrict__ Bl,
    __half* __restrict__ Whh, __half* __restrict__ Whl,
    float* __restrict__ srcp, float* __restrict__ dstp,
    const float* __restrict__ avec)
{
    extern __shared__ __align__(16) char smem[];
    __shared__ float s_a1[128], s_a2[128];
    __shared__ float s_r1[128], s_r2[128];
    const uint32_t sb = smem_u32(smem);
    const int tid  = threadIdx.x;
    const int lane = tid & 31;
    const int wid  = tid >> 5;
    const int wm   = wid >> 1;
    const int wn   = wid & 1;
    const int bz   = blockIdx.z;
    const int m0   = blockIdx.y * 128;
    const int n0   = blockIdx.x * 128;

    if (tid < 128) {
        s_a1[tid] = avec[n0 + tid];
        s_a2[tid] = avec[FDIM + n0 + tid];
    }

    const __half* Abh = Ah + (long)bz * NODES * FDIM + (long)m0 * FDIM;
    const __half* Abl = Al + (long)bz * NODES * FDIM + (long)m0 * FDIM;
    const __half* Bbh = Bh + n0;
    const __half* Bbl = Bl + n0;

    constexpr int CPP = FDIM / 64;   // 4
    constexpr int NC  = 3 * CPP;     // 12

    float acc[2][8][4];
    #pragma unroll
    for (int i = 0; i < 2; i++)
        #pragma unroll
        for (int j = 0; j < 8; j++)
            #pragma unroll
            for (int q = 0; q < 4; q++) acc[i][j][q] = 0.f;

    auto load_chunk = [&](int st, int c) {
        const int p  = c / CPP;
        const int k0 = (c % CPP) * 64;
        const __half* A = (p < 2) ? Abh : Abl;
        const __half* B = (p == 1) ? Bbl : Bbh;
        const uint32_t dA = sb + st * G1_STAGE;
        const uint32_t dB = dA + 16384;
        #pragma unroll
        for (int i = 0; i < 4; i++) {
            int idx = tid + i * 256, r = idx >> 3, s = idx & 7;
            cp16(dA + SWZA(r * 128 + s * 16), A + (long)r * FDIM + k0 + s * 8);
        }
        #pragma unroll
        for (int i = 0; i < 4; i++) {
            int idx = tid + i * 256, r = idx >> 4, s = idx & 15;
            cp16(dB + SWZB(r * 256 + s * 16), B + (long)(k0 + r) * FDIM + s * 8);
        }
        CP_COMMIT();
    };

    const int alr = lane & 15;
    const int alc = lane >> 4;

    load_chunk(0, 0);
    for (int c = 0; c < NC; ++c) {
        const int s = c & 1;
        if (c + 1 < NC) { load_chunk(s ^ 1, c + 1); CP_WAIT(1); }
        else            { CP_WAIT(0); }
        __syncthreads();
        const uint32_t sA = sb + s * G1_STAGE;
        const uint32_t sB = sA + 16384;
        #pragma unroll
        for (int kk = 0; kk < 4; kk++) {
            uint32_t a[2][4];
            #pragma unroll
            for (int mt = 0; mt < 2; mt++)
                LDSM4(a[mt], sA + SWZA((wm * 32 + mt * 16 + alr) * 128 + kk * 32 + alc * 16));
            uint32_t b[8][2];
            #pragma unroll
            for (int np = 0; np < 4; np++) {
                uint32_t t0, t1, t2, t3;
                LDSM4T(t0, t1, t2, t3,
                       sB + SWZB((kk * 16 + alr) * 256 + (wn * 64 + np * 16 + alc * 8) * 2));
                b[2 * np][0] = t0; b[2 * np][1] = t1;
                b[2 * np + 1][0] = t2; b[2 * np + 1][1] = t3;
            }
            #pragma unroll
            for (int mt = 0; mt < 2; mt++)
                #pragma unroll
                for (int nt = 0; nt < 8; nt++)
                    mma16816(acc[mt][nt], a[mt], b[nt]);
        }
        __syncthreads();
    }

    // ---- epilogue: stage hi/lo + src/dst partials ----
    if (tid < 128) { s_r1[tid] = 0.f; s_r2[tid] = 0.f; }
    __syncthreads();

    const int g  = lane >> 2;
    const int t2 = (lane & 3) * 2;
    __half2* hiT = (__half2*)(smem);
    __half2* loT = (__half2*)(smem + 32768);
    float p1[4] = {0.f, 0.f, 0.f, 0.f};
    float p2[4] = {0.f, 0.f, 0.f, 0.f};

    #pragma unroll
    for (int mt = 0; mt < 2; mt++)
        #pragma unroll
        for (int nt = 0; nt < 8; nt++) {
            const int r  = wm * 32 + mt * 16 + g;
            const int cc = wn * 64 + nt * 8 + t2;
            float v0 = acc[mt][nt][0], v1 = acc[mt][nt][1];
            float v2 = acc[mt][nt][2], v3 = acc[mt][nt][3];
            __half2 h01, l01, h23, l23;
            h01.x = __float2half(v0); h01.y = __float2half(v1);
            l01.x = __float2half(v0 - __half2float(h01.x));
            l01.y = __float2half(v1 - __half2float(h01.y));
            h23.x = __float2half(v2); h23.y = __float2half(v3);
            l23.x = __float2half(v2 - __half2float(h23.x));
            l23.y = __float2half(v3 - __half2float(h23.y));
            hiT[(r * 128 + cc) >> 1]       = h01;
            loT[(r * 128 + cc) >> 1]       = l01;
            hiT[((r + 8) * 128 + cc) >> 1] = h23;
            loT[((r + 8) * 128 + cc) >> 1] = l23;
            float a10 = s_a1[cc], a11 = s_a1[cc + 1];
            float a20 = s_a2[cc], a21 = s_a2[cc + 1];
            p1[mt * 2]     = fmaf(v0, a10, fmaf(v1, a11, p1[mt * 2]));
            p2[mt * 2]     = fmaf(v0, a20, fmaf(v1, a21, p2[mt * 2]));
            p1[mt * 2 + 1] = fmaf(v2, a10, fmaf(v3, a11, p1[mt * 2 + 1]));
            p2[mt * 2 + 1] = fmaf(v2, a20, fmaf(v3, a21, p2[mt * 2 + 1]));
        }
    #pragma unroll
    for (int mt = 0; mt < 2; mt++) {
        atomicAdd(&s_r1[wm * 32 + mt * 16 + g],     p1[mt * 2]);
        atomicAdd(&s_r1[wm * 32 + mt * 16 + g + 8], p1[mt * 2 + 1]);
        atomicAdd(&s_r2[wm * 32 + mt * 16 + g],     p2[mt * 2]);
        atomicAdd(&s_r2[wm * 32 + mt * 16 + g + 8], p2[mt * 2 + 1]);
    }
    __syncthreads();

    #pragma unroll
    for (int i = 0; i < 8; i++) {
        int idx = tid + i * 256;
        int r = idx >> 4, ch = idx & 15;
        long gofs = ((long)bz * NODES + m0 + r) * FDIM + n0 + ch * 8;
        *(uint4*)(Whh + gofs) = *(uint4*)(smem + r * 256 + ch * 16);
        *(uint4*)(Whl + gofs) = *(uint4*)(smem + 32768 + r * 256 + ch * 16);
    }
    if (tid < 128) {
        const long o = (long)blockIdx.x * NB * NODES + bz * NODES + m0 + tid;
        srcp[o] = s_r1[tid];
        dstp[o] = s_r2[tid];
    }
}

// ============================================================================
// GEMM2: out = elu(att @ Wh).  att single fp16, Wh split hi/lo -> 2 MMA parts
// per k-step into one accumulator.  grid (FDIM/128, NODES/128, NB).
// ============================================================================
#define G2_STAGE 49152          // A 16KB + Bh 16KB + Bl 16KB
#define G2_SMEM  (2 * G2_STAGE) // 96 KB
__global__ __launch_bounds__(256) void gemm2_kernel(
    const __half* __restrict__ att,
    const __half* __restrict__ Bh, const __half* __restrict__ Bl,
    float* __restrict__ outp)
{
    extern __shared__ __align__(16) char smem[];
    const uint32_t sb = smem_u32(smem);
    const int tid  = threadIdx.x;
    const int lane = tid & 31;
    const int wid  = tid >> 5;
    const int wm   = wid >> 1;
    const int wn   = wid & 1;
    const int bz   = blockIdx.z;
    const int m0   = blockIdx.y * 128;
    const int n0   = blockIdx.x * 128;

    const __half* Ab  = att + (long)bz * NODES * NODES + (long)m0 * NODES;
    const __half* Bbh = Bh + (long)bz * NODES * FDIM + n0;
    const __half* Bbl = Bl + (long)bz * NODES * FDIM + n0;

    constexpr int NC = NODES / 64;   // 8 chunks

    float acc[2][8][4];
    #pragma unroll
    for (int i = 0; i < 2; i++)
        #pragma unroll
        for (int j = 0; j < 8; j++)
            #pragma unroll
            for (int q = 0; q < 4; q++) acc[i][j][q] = 0.f;

    auto load_chunk = [&](int st, int c) {
        const int k0 = c * 64;
        const uint32_t dA  = sb + st * G2_STAGE;
        const uint32_t dBh = dA + 16384;
        const uint32_t dBl = dA + 32768;
        #pragma unroll
        for (int i = 0; i < 4; i++) {
            int idx = tid + i * 256, r = idx >> 3, s = idx & 7;
            cp16(dA + SWZA(r * 128 + s * 16), Ab + (long)r * NODES + k0 + s * 8);
        }
        #pragma unroll
        for (int i = 0; i < 4; i++) {
            int idx = tid + i * 256, r = idx >> 4, s = idx & 15;
            cp16(dBh + SWZB(r * 256 + s * 16), Bbh + (long)(k0 + r) * FDIM + s * 8);
        }
        #pragma unroll
        for (int i = 0; i < 4; i++) {
            int idx = tid + i * 256, r = idx >> 4, s = idx & 15;
            cp16(dBl + SWZB(r * 256 + s * 16), Bbl + (long)(k0 + r) * FDIM + s * 8);
        }
        CP_COMMIT();
    };

    const int alr = lane & 15;
    const int alc = lane >> 4;

    load_chunk(0, 0);
    for (int c = 0; c < NC; ++c) {
        const int s = c & 1;
        if (c + 1 < NC) { load_chunk(s ^ 1, c + 1); CP_WAIT(1); }
        else            { CP_WAIT(0); }
        __syncthreads();
        const uint32_t sA = sb + s * G2_STAGE;
        #pragma unroll
        for (int kk = 0; kk < 4; kk++) {
            uint32_t a[2][4];
            #pragma unroll
            for (int mt = 0; mt < 2; mt++)
                LDSM4(a[mt], sA + SWZA((wm * 32 + mt * 16 + alr) * 128 + kk * 32 + alc * 16));
            #pragma unroll
            for (int part = 0; part < 2; part++) {
                const uint32_t sB = sA + 16384 + part * 16384;
                uint32_t b[8][2];
                #pragma unroll
                for (int np = 0; np < 4; np++) {
                    uint32_t t0, t1, t2, t3;
                    LDSM4T(t0, t1, t2, t3,
                           sB + SWZB((kk * 16 + alr) * 256 + (wn * 64 + np * 16 + alc * 8) * 2));
                    b[2 * np][0] = t0; b[2 * np][1] = t1;
                    b[2 * np + 1][0] = t2; b[2 * np + 1][1] = t3;
                }
                #pragma unroll
                for (int mt = 0; mt < 2; mt++)
                    #pragma unroll
                    for (int nt = 0; nt < 8; nt++)
                        mma16816(acc[mt][nt], a[mt], b[nt]);
            }
        }
        __syncthreads();
    }

    const int g  = lane >> 2;
    const int t2 = (lane & 3) * 2;
    #pragma unroll
    for (int mt = 0; mt < 2; mt++)
        #pragma unroll
        for (int nt = 0; nt < 8; nt++) {
            const long base = ((long)bz * NODES + m0 + wm * 32 + mt * 16) * FDIM
                            + n0 + wn * 64 + nt * 8 + t2;
            float v0 = acc[mt][nt][0], v1 = acc[mt][nt][1];
            float v2 = acc[mt][nt][2], v3 = acc[mt][nt][3];
            float2 r01, r23;
            r01.x = v0 > 0.f ? v0 : fast_exp(v0) - 1.f;
            r01.y = v1 > 0.f ? v1 : fast_exp(v1) - 1.f;
            r23.x = v2 > 0.f ? v2 : fast_exp(v2) - 1.f;
            r23.y = v3 > 0.f ? v3 : fast_exp(v3) - 1.f;
            *(float2*)(outp + base + (long)g * FDIM)       = r01;
            *(float2*)(outp + base + (long)(g + 8) * FDIM) = r23;
        }
}

// ============================================================================
// fp32 -> fp16 hi/lo split
// ============================================================================
__global__ __launch_bounds__(256) void conv_split(const float4* __restrict__ in4,
                                                  __half* __restrict__ hh,
                                                  __half* __restrict__ hl)
{
    long i = (long)blockIdx.x * 256 + threadIdx.x;
    float4 v = in4[i];
    __half2 h0, h1, l0, l1;
    h0.x = __float2half(v.x); h0.y = __float2half(v.y);
    h1.x = __float2half(v.z); h1.y = __float2half(v.w);
    l0.x = __float2half(v.x - __half2float(h0.x));
    l0.y = __float2half(v.y - __half2float(h0.y));
    l1.x = __float2half(v.z - __half2float(h1.x));
    l1.y = __float2half(v.w - __half2float(h1.y));
    ((__half2*)hh)[2 * i] = h0; ((__half2*)hh)[2 * i + 1] = h1;
    ((__half2*)hl)[2 * i] = l0; ((__half2*)hl)[2 * i + 1] = l1;
}

// ============================================================================
// masked softmax attention -> single fp16
// ============================================================================
__global__ __launch_bounds__(512) void attn_kernel(const int* __restrict__ adj,
                                                   const float* __restrict__ srcp,
                                                   const float* __restrict__ dstp,
                                                   __half* __restrict__ att)
{
    const int i  = blockIdx.x;
    const int bn = blockIdx.y;
    const int j  = threadIdx.x;
    const int w    = threadIdx.x >> 5;
    const int lane = threadIdx.x & 31;

    __shared__ float sred[16];
    __shared__ float sbc;

    const float si = srcp[bn * NODES + i] + srcp[NB * NODES + bn * NODES + i];
    const float dj = dstp[bn * NODES + j] + dstp[NB * NODES + bn * NODES + j];
    const int adjv = adj[i * NODES + j];
    float e = si + dj;
    e = e > 0.f ? e : ALPHA * e;
    e = (adjv > 0) ? e : MASK_VAL;

    float mx = e;
    #pragma unroll
    for (int o = 16; o; o >>= 1) mx = fmaxf(mx, __shfl_xor_sync(0xffffffffu, mx, o));
    if (lane == 0) sred[w] = mx;
    __syncthreads();
    if (threadIdx.x == 0) {
        float v = sred[0];
        #pragma unroll
        for (int k = 1; k < 16; k++) v = fmaxf(v, sred[k]);
        sbc = v;
    }
    __syncthreads();
    mx = sbc;

    const float p = (adjv > 0) ? fast_exp(e - mx) : 0.f;

    float sm = p;
    #pragma unroll
    for (int o = 16; o; o >>= 1) sm += __shfl_xor_sync(0xffffffffu, sm, o);
    __syncthreads();
    if (lane == 0) sred[w] = sm;
    __syncthreads();
    if (threadIdx.x == 0) {
        float v = 0.f;
        #pragma unroll
        for (int k = 0; k < 16; k++) v += sred[k];
        sbc = v;
    }
    __syncthreads();

    att[((long)bn * NODES + i) * NODES + j] = __float2half(p / sbc);
}

// ============================================================================
extern "C" void kernel_launch(void* const* d_in, const int* in_sizes, int n_in,
                              void* d_out, int out_size)
{
    const float* h   = (const float*)d_in[0];
    const int*   adj = (const int*)d_in[1];
    const float* W   = (const float*)d_in[2];
    const float* a   = (const float*)d_in[3];
    float* out = (float*)d_out;

    __half *hh, *hl, *atp, *wh, *wl, *whh, *whl;
    float *srcp, *dstp;
    cudaGetSymbolAddress((void**)&hh,  g_h_hi);
    cudaGetSymbolAddress((void**)&hl,  g_h_lo);
    cudaGetSymbolAddress((void**)&atp, g_att);
    cudaGetSymbolAddress((void**)&wh,  g_W_hi);
    cudaGetSymbolAddress((void**)&wl,  g_W_lo);
    cudaGetSymbolAddress((void**)&whh, g_Wh_hi);
    cudaGetSymbolAddress((void**)&whl, g_Wh_lo);
    cudaGetSymbolAddress((void**)&srcp, g_srcp);
    cudaGetSymbolAddress((void**)&dstp, g_dstp);

    cudaFuncSetAttribute(gemm1_kernel, cudaFuncAttributeMaxDynamicSharedMemorySize, G1_SMEM);
    cudaFuncSetAttribute(gemm2_kernel, cudaFuncAttributeMaxDynamicSharedMemorySize, G2_SMEM);

    // 1) fp32 -> fp16 hi/lo
    conv_split<<<(NB * NODES * FDIM) / (4 * 256), 256>>>((const float4*)h, hh, hl);
    conv_split<<<(FDIM * FDIM) / (4 * 256), 256>>>((const float4*)W, wh, wl);

    // 2) GEMM1 (3-pass fp16) + fused src/dst epilogue
    {
        dim3 grid(FDIM / 128, NODES / 128, NB);
        gemm1_kernel<<<grid, 256, G1_SMEM>>>(hh, hl, wh, wl, whh, whl, srcp, dstp, a);
    }

    // 3) masked softmax -> att fp16
    {
        dim3 grid(NODES, NB);
        attn_kernel<<<grid, 512>>>(adj, srcp, dstp, atp);
    }

    // 4) GEMM2 (2-part fp16) + ELU
    {
        dim3 grid(FDIM / 128, NODES / 128, NB);
        gemm2_kernel<<<grid, 256, G2_SMEM>>>(atp, whh, whl, out);
    }
}

// round 6
// speedup vs baseline: 2.7056x; 1.3471x over previous
#include <cuda_runtime.h>
#include <cuda_fp16.h>
#include <cstdint>
#include <math.h>

#define NB    64
#define NODES 512
#define FDIM  256
#define ALPHA 0.2f
#define MASK_VAL -9000000000000000.0f

// ---------------- scratch ----------------
__device__ __half g_h_hi [NB * NODES * FDIM];
__device__ __half g_h_lo [NB * NODES * FDIM];
__device__ __half g_att  [NB * NODES * NODES];
__device__ __half g_Wh_hi[NB * NODES * FDIM];
__device__ __half g_Wh_lo[NB * NODES * FDIM];
__device__ __half g_W_hi [FDIM * FDIM];
__device__ __half g_W_lo [FDIM * FDIM];
__device__ float  g_srcp[2 * NB * NODES];   // per n-half partials
__device__ float  g_dstp[2 * NB * NODES];

// ---------------- helpers ----------------
__device__ __forceinline__ uint32_t smem_u32(const void* p) {
    uint32_t a;
    asm("{ .reg .u64 t; cvta.to.shared.u64 t, %1; cvt.u32.u64 %0, t; }" : "=r"(a) : "l"(p));
    return a;
}
__device__ __forceinline__ void cp16(uint32_t d, const void* g) {
    asm volatile("cp.async.cg.shared.global [%0], [%1], 16;" :: "r"(d), "l"(g));
}
#define CP_COMMIT() asm volatile("cp.async.commit_group;" ::: "memory")
#define CP_WAIT(n)  asm volatile("cp.async.wait_group %0;" :: "n"(n) : "memory")

#define LDSM4(r, addr)                                                       \
    asm volatile("ldmatrix.sync.aligned.m8n8.x4.shared.b16 {%0,%1,%2,%3}, [%4];" \
        : "=r"((r)[0]), "=r"((r)[1]), "=r"((r)[2]), "=r"((r)[3]) : "r"(addr))
#define LDSM4T(r0, r1, r2, r3, addr)                                         \
    asm volatile("ldmatrix.sync.aligned.m8n8.x4.trans.shared.b16 {%0,%1,%2,%3}, [%4];" \
        : "=r"(r0), "=r"(r1), "=r"(r2), "=r"(r3) : "r"(addr))

__device__ __forceinline__ void mma16816(float* d, const uint32_t* a, const uint32_t* b) {
    asm volatile(
        "mma.sync.aligned.m16n8k16.row.col.f32.f16.f16.f32 "
        "{%0,%1,%2,%3}, {%4,%5,%6,%7}, {%8,%9}, {%0,%1,%2,%3};"
        : "+f"(d[0]), "+f"(d[1]), "+f"(d[2]), "+f"(d[3])
        : "r"(a[0]), "r"(a[1]), "r"(a[2]), "r"(a[3]), "r"(b[0]), "r"(b[1]));
}

#define SWZA(x) ((x) ^ (((x) >> 3) & 0x70))
#define SWZB(x) ((x) ^ (((x) >> 4) & 0x70))

// FMA-only exp (fine for |x| < ~80)
__device__ __forceinline__ float fast_exp(float x) {
    x = fmaxf(x, -80.0f);
    float n = rintf(x * 1.442695041f);
    float r = fmaf(n, -0.693359375f, x);
    r = fmaf(n, 2.12194440e-4f, r);
    float p = 1.9875691500E-4f;
    p = fmaf(p, r, 1.3981999507E-3f);
    p = fmaf(p, r, 8.3334519073E-3f);
    p = fmaf(p, r, 4.1665795894E-2f);
    p = fmaf(p, r, 1.6666665459E-1f);
    p = fmaf(p, r, 5.0000001201E-1f);
    float z = fmaf(p * r, r, r) + 1.0f;
    return z * __int_as_float(((int)n + 127) << 23);
}

// ============================================================================
// GEMM1: Wh = h @ W, fp16 split 3-pass (Ah·Bh + Ah·Bl + Al·Bh).
// Epilogue: write Wh fp16 hi/lo + fused src/dst partial dots.
// ============================================================================
#define G1_STAGE 32768
#define G1_SMEM  (2 * G1_STAGE)
__global__ __launch_bounds__(256) void gemm1_kernel(
    const __half* __restrict__ Ah, const __half* __restrict__ Al,
    const __half* __restrict__ Bh, const __half* __restrict__ Bl,
    __half* __restrict__ Whh, __half* __restrict__ Whl,
    float* __restrict__ srcp, float* __restrict__ dstp,
    const float* __restrict__ avec)
{
    extern __shared__ __align__(16) char smem[];
    __shared__ float s_a1[128], s_a2[128];
    __shared__ float s_r1[128], s_r2[128];
    const uint32_t sb = smem_u32(smem);
    const int tid  = threadIdx.x;
    const int lane = tid & 31;
    const int wid  = tid >> 5;
    const int wm   = wid >> 1;
    const int wn   = wid & 1;
    const int bz   = blockIdx.z;
    const int m0   = blockIdx.y * 128;
    const int n0   = blockIdx.x * 128;

    if (tid < 128) {
        s_a1[tid] = avec[n0 + tid];
        s_a2[tid] = avec[FDIM + n0 + tid];
    }

    const __half* Abh = Ah + (long)bz * NODES * FDIM + (long)m0 * FDIM;
    const __half* Abl = Al + (long)bz * NODES * FDIM + (long)m0 * FDIM;
    const __half* Bbh = Bh + n0;
    const __half* Bbl = Bl + n0;

    constexpr int CPP = FDIM / 64;
    constexpr int NC  = 3 * CPP;

    float acc[2][8][4];
    #pragma unroll
    for (int i = 0; i < 2; i++)
        #pragma unroll
        for (int j = 0; j < 8; j++)
            #pragma unroll
            for (int q = 0; q < 4; q++) acc[i][j][q] = 0.f;

    auto load_chunk = [&](int st, int c) {
        const int p  = c / CPP;
        const int k0 = (c % CPP) * 64;
        const __half* A = (p < 2) ? Abh : Abl;
        const __half* B = (p == 1) ? Bbl : Bbh;
        const uint32_t dA = sb + st * G1_STAGE;
        const uint32_t dB = dA + 16384;
        #pragma unroll
        for (int i = 0; i < 4; i++) {
            int idx = tid + i * 256, r = idx >> 3, s = idx & 7;
            cp16(dA + SWZA(r * 128 + s * 16), A + (long)r * FDIM + k0 + s * 8);
        }
        #pragma unroll
        for (int i = 0; i < 4; i++) {
            int idx = tid + i * 256, r = idx >> 4, s = idx & 15;
            cp16(dB + SWZB(r * 256 + s * 16), B + (long)(k0 + r) * FDIM + s * 8);
        }
        CP_COMMIT();
    };

    const int alr = lane & 15;
    const int alc = lane >> 4;

    load_chunk(0, 0);
    for (int c = 0; c < NC; ++c) {
        const int s = c & 1;
        if (c + 1 < NC) { load_chunk(s ^ 1, c + 1); CP_WAIT(1); }
        else            { CP_WAIT(0); }
        __syncthreads();
        const uint32_t sA = sb + s * G1_STAGE;
        const uint32_t sB = sA + 16384;
        #pragma unroll
        for (int kk = 0; kk < 4; kk++) {
            uint32_t a[2][4];
            #pragma unroll
            for (int mt = 0; mt < 2; mt++)
                LDSM4(a[mt], sA + SWZA((wm * 32 + mt * 16 + alr) * 128 + kk * 32 + alc * 16));
            uint32_t b[8][2];
            #pragma unroll
            for (int np = 0; np < 4; np++) {
                uint32_t t0, t1, t2, t3;
                LDSM4T(t0, t1, t2, t3,
                       sB + SWZB((kk * 16 + alr) * 256 + (wn * 64 + np * 16 + alc * 8) * 2));
                b[2 * np][0] = t0; b[2 * np][1] = t1;
                b[2 * np + 1][0] = t2; b[2 * np + 1][1] = t3;
            }
            #pragma unroll
            for (int mt = 0; mt < 2; mt++)
                #pragma unroll
                for (int nt = 0; nt < 8; nt++)
                    mma16816(acc[mt][nt], a[mt], b[nt]);
        }
        __syncthreads();
    }

    if (tid < 128) { s_r1[tid] = 0.f; s_r2[tid] = 0.f; }
    __syncthreads();

    const int g  = lane >> 2;
    const int t2 = (lane & 3) * 2;
    __half2* hiT = (__half2*)(smem);
    __half2* loT = (__half2*)(smem + 32768);
    float p1[4] = {0.f, 0.f, 0.f, 0.f};
    float p2[4] = {0.f, 0.f, 0.f, 0.f};

    #pragma unroll
    for (int mt = 0; mt < 2; mt++)
        #pragma unroll
        for (int nt = 0; nt < 8; nt++) {
            const int r  = wm * 32 + mt * 16 + g;
            const int cc = wn * 64 + nt * 8 + t2;
            float v0 = acc[mt][nt][0], v1 = acc[mt][nt][1];
            float v2 = acc[mt][nt][2], v3 = acc[mt][nt][3];
            __half2 h01, l01, h23, l23;
            h01.x = __float2half(v0); h01.y = __float2half(v1);
            l01.x = __float2half(v0 - __half2float(h01.x));
            l01.y = __float2half(v1 - __half2float(h01.y));
            h23.x = __float2half(v2); h23.y = __float2half(v3);
            l23.x = __float2half(v2 - __half2float(h23.x));
            l23.y = __float2half(v3 - __half2float(h23.y));
            hiT[(r * 128 + cc) >> 1]       = h01;
            loT[(r * 128 + cc) >> 1]       = l01;
            hiT[((r + 8) * 128 + cc) >> 1] = h23;
            loT[((r + 8) * 128 + cc) >> 1] = l23;
            float a10 = s_a1[cc], a11 = s_a1[cc + 1];
            float a20 = s_a2[cc], a21 = s_a2[cc + 1];
            p1[mt * 2]     = fmaf(v0, a10, fmaf(v1, a11, p1[mt * 2]));
            p2[mt * 2]     = fmaf(v0, a20, fmaf(v1, a21, p2[mt * 2]));
            p1[mt * 2 + 1] = fmaf(v2, a10, fmaf(v3, a11, p1[mt * 2 + 1]));
            p2[mt * 2 + 1] = fmaf(v2, a20, fmaf(v3, a21, p2[mt * 2 + 1]));
        }
    #pragma unroll
    for (int mt = 0; mt < 2; mt++) {
        atomicAdd(&s_r1[wm * 32 + mt * 16 + g],     p1[mt * 2]);
        atomicAdd(&s_r1[wm * 32 + mt * 16 + g + 8], p1[mt * 2 + 1]);
        atomicAdd(&s_r2[wm * 32 + mt * 16 + g],     p2[mt * 2]);
        atomicAdd(&s_r2[wm * 32 + mt * 16 + g + 8], p2[mt * 2 + 1]);
    }
    __syncthreads();

    #pragma unroll
    for (int i = 0; i < 8; i++) {
        int idx = tid + i * 256;
        int r = idx >> 4, ch = idx & 15;
        long gofs = ((long)bz * NODES + m0 + r) * FDIM + n0 + ch * 8;
        *(uint4*)(Whh + gofs) = *(uint4*)(smem + r * 256 + ch * 16);
        *(uint4*)(Whl + gofs) = *(uint4*)(smem + 32768 + r * 256 + ch * 16);
    }
    if (tid < 128) {
        const long o = (long)blockIdx.x * NB * NODES + bz * NODES + m0 + tid;
        srcp[o] = s_r1[tid];
        dstp[o] = s_r2[tid];
    }
}

// ============================================================================
// GEMM2: out = elu(att @ Wh).  att single fp16, Wh split hi/lo (2-part).
// ============================================================================
#define G2_STAGE 49152
#define G2_SMEM  (2 * G2_STAGE)
__global__ __launch_bounds__(256) void gemm2_kernel(
    const __half* __restrict__ att,
    const __half* __restrict__ Bh, const __half* __restrict__ Bl,
    float* __restrict__ outp)
{
    extern __shared__ __align__(16) char smem[];
    const uint32_t sb = smem_u32(smem);
    const int tid  = threadIdx.x;
    const int lane = tid & 31;
    const int wid  = tid >> 5;
    const int wm   = wid >> 1;
    const int wn   = wid & 1;
    const int bz   = blockIdx.z;
    const int m0   = blockIdx.y * 128;
    const int n0   = blockIdx.x * 128;

    const __half* Ab  = att + (long)bz * NODES * NODES + (long)m0 * NODES;
    const __half* Bbh = Bh + (long)bz * NODES * FDIM + n0;
    const __half* Bbl = Bl + (long)bz * NODES * FDIM + n0;

    constexpr int NC = NODES / 64;

    float acc[2][8][4];
    #pragma unroll
    for (int i = 0; i < 2; i++)
        #pragma unroll
        for (int j = 0; j < 8; j++)
            #pragma unroll
            for (int q = 0; q < 4; q++) acc[i][j][q] = 0.f;

    auto load_chunk = [&](int st, int c) {
        const int k0 = c * 64;
        const uint32_t dA  = sb + st * G2_STAGE;
        const uint32_t dBh = dA + 16384;
        const uint32_t dBl = dA + 32768;
        #pragma unroll
        for (int i = 0; i < 4; i++) {
            int idx = tid + i * 256, r = idx >> 3, s = idx & 7;
            cp16(dA + SWZA(r * 128 + s * 16), Ab + (long)r * NODES + k0 + s * 8);
        }
        #pragma unroll
        for (int i = 0; i < 4; i++) {
            int idx = tid + i * 256, r = idx >> 4, s = idx & 15;
            cp16(dBh + SWZB(r * 256 + s * 16), Bbh + (long)(k0 + r) * FDIM + s * 8);
        }
        #pragma unroll
        for (int i = 0; i < 4; i++) {
            int idx = tid + i * 256, r = idx >> 4, s = idx & 15;
            cp16(dBl + SWZB(r * 256 + s * 16), Bbl + (long)(k0 + r) * FDIM + s * 8);
        }
        CP_COMMIT();
    };

    const int alr = lane & 15;
    const int alc = lane >> 4;

    load_chunk(0, 0);
    for (int c = 0; c < NC; ++c) {
        const int s = c & 1;
        if (c + 1 < NC) { load_chunk(s ^ 1, c + 1); CP_WAIT(1); }
        else            { CP_WAIT(0); }
        __syncthreads();
        const uint32_t sA = sb + s * G2_STAGE;
        #pragma unroll
        for (int kk = 0; kk < 4; kk++) {
            uint32_t a[2][4];
            #pragma unroll
            for (int mt = 0; mt < 2; mt++)
                LDSM4(a[mt], sA + SWZA((wm * 32 + mt * 16 + alr) * 128 + kk * 32 + alc * 16));
            #pragma unroll
            for (int part = 0; part < 2; part++) {
                const uint32_t sB = sA + 16384 + part * 16384;
                uint32_t b[8][2];
                #pragma unroll
                for (int np = 0; np < 4; np++) {
                    uint32_t t0, t1, t2, t3;
                    LDSM4T(t0, t1, t2, t3,
                           sB + SWZB((kk * 16 + alr) * 256 + (wn * 64 + np * 16 + alc * 8) * 2));
                    b[2 * np][0] = t0; b[2 * np][1] = t1;
                    b[2 * np + 1][0] = t2; b[2 * np + 1][1] = t3;
                }
                #pragma unroll
                for (int mt = 0; mt < 2; mt++)
                    #pragma unroll
                    for (int nt = 0; nt < 8; nt++)
                        mma16816(acc[mt][nt], a[mt], b[nt]);
            }
        }
        __syncthreads();
    }

    const int g  = lane >> 2;
    const int t2 = (lane & 3) * 2;
    #pragma unroll
    for (int mt = 0; mt < 2; mt++)
        #pragma unroll
        for (int nt = 0; nt < 8; nt++) {
            const long base = ((long)bz * NODES + m0 + wm * 32 + mt * 16) * FDIM
                            + n0 + wn * 64 + nt * 8 + t2;
            float v0 = acc[mt][nt][0], v1 = acc[mt][nt][1];
            float v2 = acc[mt][nt][2], v3 = acc[mt][nt][3];
            float2 r01, r23;
            r01.x = v0 > 0.f ? v0 : fast_exp(v0) - 1.f;
            r01.y = v1 > 0.f ? v1 : fast_exp(v1) - 1.f;
            r23.x = v2 > 0.f ? v2 : fast_exp(v2) - 1.f;
            r23.y = v3 > 0.f ? v3 : fast_exp(v3) - 1.f;
            *(float2*)(outp + base + (long)g * FDIM)       = r01;
            *(float2*)(outp + base + (long)(g + 8) * FDIM) = r23;
        }
}

// ============================================================================
// fp32 -> fp16 hi/lo split
// ============================================================================
__global__ __launch_bounds__(256) void conv_split(const float4* __restrict__ in4,
                                                  __half* __restrict__ hh,
                                                  __half* __restrict__ hl)
{
    long i = (long)blockIdx.x * 256 + threadIdx.x;
    float4 v = in4[i];
    __half2 h0, h1, l0, l1;
    h0.x = __float2half(v.x); h0.y = __float2half(v.y);
    h1.x = __float2half(v.z); h1.y = __float2half(v.w);
    l0.x = __float2half(v.x - __half2float(h0.x));
    l0.y = __float2half(v.y - __half2float(h0.y));
    l1.x = __float2half(v.z - __half2float(h1.x));
    l1.y = __float2half(v.w - __half2float(h1.y));
    ((__half2*)hh)[2 * i] = h0; ((__half2*)hh)[2 * i + 1] = h1;
    ((__half2*)hl)[2 * i] = l0; ((__half2*)hl)[2 * i + 1] = l1;
}

// ============================================================================
// Warp-per-row masked softmax: 16 j's per thread, registers only.
// No max pass (|e| <= ~40 fits fp32 exp comfortably); masked -> p = 0.
// ============================================================================
__global__ __launch_bounds__(256) void attn_kernel(const int* __restrict__ adj,
                                                   const float* __restrict__ srcp,
                                                   const float* __restrict__ dstp,
                                                   __half* __restrict__ att)
{
    const int warp = threadIdx.x >> 5;
    const int lane = threadIdx.x & 31;
    const int row  = blockIdx.x * 8 + warp;       // 0 .. NB*NODES-1
    const int bn   = row >> 9;
    const int i    = row & (NODES - 1);

    const float si = srcp[bn * NODES + i] + srcp[NB * NODES + bn * NODES + i];
    const int4*   adj4 = (const int4*)(adj + i * NODES);
    const float4* d1v  = (const float4*)(dstp + bn * NODES);
    const float4* d2v  = (const float4*)(dstp + NB * NODES + bn * NODES);

    float p[16];
    float sum = 0.f;
    #pragma unroll
    for (int k = 0; k < 4; k++) {
        const int q = lane * 4 + k;               // int4 / float4 index
        int4   av = adj4[q];
        float4 a1 = d1v[q];
        float4 a2 = d2v[q];
        float e0 = si + a1.x + a2.x; e0 = e0 > 0.f ? e0 : ALPHA * e0;
        float e1 = si + a1.y + a2.y; e1 = e1 > 0.f ? e1 : ALPHA * e1;
        float e2 = si + a1.z + a2.z; e2 = e2 > 0.f ? e2 : ALPHA * e2;
        float e3 = si + a1.w + a2.w; e3 = e3 > 0.f ? e3 : ALPHA * e3;
        p[k * 4 + 0] = (av.x > 0) ? fast_exp(e0) : 0.f;
        p[k * 4 + 1] = (av.y > 0) ? fast_exp(e1) : 0.f;
        p[k * 4 + 2] = (av.z > 0) ? fast_exp(e2) : 0.f;
        p[k * 4 + 3] = (av.w > 0) ? fast_exp(e3) : 0.f;
        sum += p[k * 4 + 0] + p[k * 4 + 1] + p[k * 4 + 2] + p[k * 4 + 3];
    }
    #pragma unroll
    for (int o = 16; o; o >>= 1) sum += __shfl_xor_sync(0xffffffffu, sum, o);
    const float rinv = __frcp_rn(sum);

    __half2 h2[8];
    #pragma unroll
    for (int k = 0; k < 8; k++) {
        h2[k].x = __float2half(p[2 * k] * rinv);
        h2[k].y = __float2half(p[2 * k + 1] * rinv);
    }
    uint4* dst = (uint4*)(att + ((long)bn * NODES + i) * NODES + lane * 16);
    dst[0] = *(uint4*)&h2[0];
    dst[1] = *(uint4*)&h2[4];
}

// ============================================================================
extern "C" void kernel_launch(void* const* d_in, const int* in_sizes, int n_in,
                              void* d_out, int out_size)
{
    const float* h   = (const float*)d_in[0];
    const int*   adj = (const int*)d_in[1];
    const float* W   = (const float*)d_in[2];
    const float* a   = (const float*)d_in[3];
    float* out = (float*)d_out;

    __half *hh, *hl, *atp, *wh, *wl, *whh, *whl;
    float *srcp, *dstp;
    cudaGetSymbolAddress((void**)&hh,  g_h_hi);
    cudaGetSymbolAddress((void**)&hl,  g_h_lo);
    cudaGetSymbolAddress((void**)&atp, g_att);
    cudaGetSymbolAddress((void**)&wh,  g_W_hi);
    cudaGetSymbolAddress((void**)&wl,  g_W_lo);
    cudaGetSymbolAddress((void**)&whh, g_Wh_hi);
    cudaGetSymbolAddress((void**)&whl, g_Wh_lo);
    cudaGetSymbolAddress((void**)&srcp, g_srcp);
    cudaGetSymbolAddress((void**)&dstp, g_dstp);

    cudaFuncSetAttribute(gemm1_kernel, cudaFuncAttributeMaxDynamicSharedMemorySize, G1_SMEM);
    cudaFuncSetAttribute(gemm2_kernel, cudaFuncAttributeMaxDynamicSharedMemorySize, G2_SMEM);

    // 1) fp32 -> fp16 hi/lo
    conv_split<<<(NB * NODES * FDIM) / (4 * 256), 256>>>((const float4*)h, hh, hl);
    conv_split<<<(FDIM * FDIM) / (4 * 256), 256>>>((const float4*)W, wh, wl);

    // 2) GEMM1 (3-pass fp16) + fused src/dst epilogue
    {
        dim3 grid(FDIM / 128, NODES / 128, NB);
        gemm1_kernel<<<grid, 256, G1_SMEM>>>(hh, hl, wh, wl, whh, whl, srcp, dstp, a);
    }

    // 3) masked softmax -> att fp16 (warp per row)
    attn_kernel<<<NB * NODES / 8, 256>>>(adj, srcp, dstp, atp);

    // 4) GEMM2 (2-part fp16) + ELU
    {
        dim3 grid(FDIM / 128, NODES / 128, NB);
        gemm2_kernel<<<grid, 256, G2_SMEM>>>(atp, whh, whl, out);
    }
}

// round 7
// speedup vs baseline: 2.8845x; 1.0661x over previous
#include <cuda_runtime.h>
#include <cuda_fp16.h>
#include <cstdint>
#include <math.h>

#define NB    64
#define NODES 512
#define FDIM  256
#define ALPHA 0.2f

// ---------------- scratch ----------------
__device__ __half g_h_hi [NB * NODES * FDIM];
__device__ __half g_h_lo [NB * NODES * FDIM];
__device__ __half g_att  [NB * NODES * NODES];
__device__ __half g_Wh_hi[NB * NODES * FDIM];
__device__ __half g_Wh_lo[NB * NODES * FDIM];
__device__ __half g_W_hi [FDIM * FDIM];
__device__ __half g_W_lo [FDIM * FDIM];
__device__ float  g_srcp[2 * NB * NODES];
__device__ float  g_dstp[2 * NB * NODES];

// ---------------- helpers ----------------
__device__ __forceinline__ uint32_t smem_u32(const void* p) {
    uint32_t a;
    asm("{ .reg .u64 t; cvta.to.shared.u64 t, %1; cvt.u32.u64 %0, t; }" : "=r"(a) : "l"(p));
    return a;
}
__device__ __forceinline__ void cp16(uint32_t d, const void* g) {
    asm volatile("cp.async.cg.shared.global [%0], [%1], 16;" :: "r"(d), "l"(g));
}
#define CP_COMMIT() asm volatile("cp.async.commit_group;" ::: "memory")
#define CP_WAIT(n)  asm volatile("cp.async.wait_group %0;" :: "n"(n) : "memory")

#define LDSM4(r, addr)                                                       \
    asm volatile("ldmatrix.sync.aligned.m8n8.x4.shared.b16 {%0,%1,%2,%3}, [%4];" \
        : "=r"((r)[0]), "=r"((r)[1]), "=r"((r)[2]), "=r"((r)[3]) : "r"(addr))
#define LDSM4T(r0, r1, r2, r3, addr)                                         \
    asm volatile("ldmatrix.sync.aligned.m8n8.x4.trans.shared.b16 {%0,%1,%2,%3}, [%4];" \
        : "=r"(r0), "=r"(r1), "=r"(r2), "=r"(r3) : "r"(addr))

__device__ __forceinline__ void mma16816(float* d, const uint32_t* a, const uint32_t* b) {
    asm volatile(
        "mma.sync.aligned.m16n8k16.row.col.f32.f16.f16.f32 "
        "{%0,%1,%2,%3}, {%4,%5,%6,%7}, {%8,%9}, {%0,%1,%2,%3};"
        : "+f"(d[0]), "+f"(d[1]), "+f"(d[2]), "+f"(d[3])
        : "r"(a[0]), "r"(a[1]), "r"(a[2]), "r"(a[3]), "r"(b[0]), "r"(b[1]));
}

#define SWZA(x) ((x) ^ (((x) >> 3) & 0x70))
#define SWZB(x) ((x) ^ (((x) >> 4) & 0x70))

// FMA-only exp
__device__ __forceinline__ float fast_exp(float x) {
    x = fmaxf(x, -80.0f);
    float n = rintf(x * 1.442695041f);
    float r = fmaf(n, -0.693359375f, x);
    r = fmaf(n, 2.12194440e-4f, r);
    float p = 1.9875691500E-4f;
    p = fmaf(p, r, 1.3981999507E-3f);
    p = fmaf(p, r, 8.3334519073E-3f);
    p = fmaf(p, r, 4.1665795894E-2f);
    p = fmaf(p, r, 1.6666665459E-1f);
    p = fmaf(p, r, 5.0000001201E-1f);
    float z = fmaf(p * r, r, r) + 1.0f;
    return z * __int_as_float(((int)n + 127) << 23);
}

// ============================================================================
// GEMM1: 3-pass split fp16, 3-stage cp.async pipeline, 1 barrier/chunk.
// ============================================================================
#define G1_STAGE 32768
#define G1_SMEM  (3 * G1_STAGE)
__global__ __launch_bounds__(256) void gemm1_kernel(
    const __half* __restrict__ Ah, const __half* __restrict__ Al,
    const __half* __restrict__ Bh, const __half* __restrict__ Bl,
    __half* __restrict__ Whh, __half* __restrict__ Whl,
    float* __restrict__ srcp, float* __restrict__ dstp,
    const float* __restrict__ avec)
{
    extern __shared__ __align__(16) char smem[];
    __shared__ float s_a1[128], s_a2[128];
    __shared__ float s_r1[128], s_r2[128];
    const uint32_t sb = smem_u32(smem);
    const int tid  = threadIdx.x;
    const int lane = tid & 31;
    const int wid  = tid >> 5;
    const int wm   = wid >> 1;
    const int wn   = wid & 1;
    const int bz   = blockIdx.z;
    const int m0   = blockIdx.y * 128;
    const int n0   = blockIdx.x * 128;

    if (tid < 128) {
        s_a1[tid] = avec[n0 + tid];
        s_a2[tid] = avec[FDIM + n0 + tid];
    }

    const __half* Abh = Ah + (long)bz * NODES * FDIM + (long)m0 * FDIM;
    const __half* Abl = Al + (long)bz * NODES * FDIM + (long)m0 * FDIM;
    const __half* Bbh = Bh + n0;
    const __half* Bbl = Bl + n0;

    constexpr int CPP = FDIM / 64;
    constexpr int NC  = 3 * CPP;

    float acc[2][8][4];
    #pragma unroll
    for (int i = 0; i < 2; i++)
        #pragma unroll
        for (int j = 0; j < 8; j++)
            #pragma unroll
            for (int q = 0; q < 4; q++) acc[i][j][q] = 0.f;

    auto load_chunk = [&](int st, int c) {
        const int p  = c / CPP;
        const int k0 = (c % CPP) * 64;
        const __half* A = (p < 2) ? Abh : Abl;
        const __half* B = (p == 1) ? Bbl : Bbh;
        const uint32_t dA = sb + st * G1_STAGE;
        const uint32_t dB = dA + 16384;
        #pragma unroll
        for (int i = 0; i < 4; i++) {
            int idx = tid + i * 256, r = idx >> 3, s = idx & 7;
            cp16(dA + SWZA(r * 128 + s * 16), A + (long)r * FDIM + k0 + s * 8);
        }
        #pragma unroll
        for (int i = 0; i < 4; i++) {
            int idx = tid + i * 256, r = idx >> 4, s = idx & 15;
            cp16(dB + SWZB(r * 256 + s * 16), B + (long)(k0 + r) * FDIM + s * 8);
        }
        CP_COMMIT();
    };

    const int alr = lane & 15;
    const int alc = lane >> 4;

    load_chunk(0, 0);
    load_chunk(1, 1);
    for (int c = 0; c < NC; ++c) {
        if (c + 1 < NC) { CP_WAIT(1); } else { CP_WAIT(0); }
        __syncthreads();
        if (c + 2 < NC) load_chunk((c + 2) % 3, c + 2);

        const uint32_t sA = sb + (c % 3) * G1_STAGE;
        const uint32_t sB = sA + 16384;
        #pragma unroll
        for (int kk = 0; kk < 4; kk++) {
            uint32_t a[2][4];
            #pragma unroll
            for (int mt = 0; mt < 2; mt++)
                LDSM4(a[mt], sA + SWZA((wm * 32 + mt * 16 + alr) * 128 + kk * 32 + alc * 16));
            uint32_t b[8][2];
            #pragma unroll
            for (int np = 0; np < 4; np++) {
                uint32_t t0, t1, t2, t3;
                LDSM4T(t0, t1, t2, t3,
                       sB + SWZB((kk * 16 + alr) * 256 + (wn * 64 + np * 16 + alc * 8) * 2));
                b[2 * np][0] = t0; b[2 * np][1] = t1;
                b[2 * np + 1][0] = t2; b[2 * np + 1][1] = t3;
            }
            #pragma unroll
            for (int mt = 0; mt < 2; mt++)
                #pragma unroll
                for (int nt = 0; nt < 8; nt++)
                    mma16816(acc[mt][nt], a[mt], b[nt]);
        }
    }

    __syncthreads();
    if (tid < 128) { s_r1[tid] = 0.f; s_r2[tid] = 0.f; }
    __syncthreads();

    const int g  = lane >> 2;
    const int t2 = (lane & 3) * 2;
    __half2* hiT = (__half2*)(smem);
    __half2* loT = (__half2*)(smem + 32768);
    float p1[4] = {0.f, 0.f, 0.f, 0.f};
    float p2[4] = {0.f, 0.f, 0.f, 0.f};

    #pragma unroll
    for (int mt = 0; mt < 2; mt++)
        #pragma unroll
        for (int nt = 0; nt < 8; nt++) {
            const int r  = wm * 32 + mt * 16 + g;
            const int cc = wn * 64 + nt * 8 + t2;
            float v0 = acc[mt][nt][0], v1 = acc[mt][nt][1];
            float v2 = acc[mt][nt][2], v3 = acc[mt][nt][3];
            __half2 h01, l01, h23, l23;
            h01.x = __float2half(v0); h01.y = __float2half(v1);
            l01.x = __float2half(v0 - __half2float(h01.x));
            l01.y = __float2half(v1 - __half2float(h01.y));
            h23.x = __float2half(v2); h23.y = __float2half(v3);
            l23.x = __float2half(v2 - __half2float(h23.x));
            l23.y = __float2half(v3 - __half2float(h23.y));
            hiT[(r * 128 + cc) >> 1]       = h01;
            loT[(r * 128 + cc) >> 1]       = l01;
            hiT[((r + 8) * 128 + cc) >> 1] = h23;
            loT[((r + 8) * 128 + cc) >> 1] = l23;
            float a10 = s_a1[cc], a11 = s_a1[cc + 1];
            float a20 = s_a2[cc], a21 = s_a2[cc + 1];
            p1[mt * 2]     = fmaf(v0, a10, fmaf(v1, a11, p1[mt * 2]));
            p2[mt * 2]     = fmaf(v0, a20, fmaf(v1, a21, p2[mt * 2]));
            p1[mt * 2 + 1] = fmaf(v2, a10, fmaf(v3, a11, p1[mt * 2 + 1]));
            p2[mt * 2 + 1] = fmaf(v2, a20, fmaf(v3, a21, p2[mt * 2 + 1]));
        }
    #pragma unroll
    for (int mt = 0; mt < 2; mt++) {
        atomicAdd(&s_r1[wm * 32 + mt * 16 + g],     p1[mt * 2]);
        atomicAdd(&s_r1[wm * 32 + mt * 16 + g + 8], p1[mt * 2 + 1]);
        atomicAdd(&s_r2[wm * 32 + mt * 16 + g],     p2[mt * 2]);
        atomicAdd(&s_r2[wm * 32 + mt * 16 + g + 8], p2[mt * 2 + 1]);
    }
    __syncthreads();

    #pragma unroll
    for (int i = 0; i < 8; i++) {
        int idx = tid + i * 256;
        int r = idx >> 4, ch = idx & 15;
        long gofs = ((long)bz * NODES + m0 + r) * FDIM + n0 + ch * 8;
        *(uint4*)(Whh + gofs) = *(uint4*)(smem + r * 256 + ch * 16);
        *(uint4*)(Whl + gofs) = *(uint4*)(smem + 32768 + r * 256 + ch * 16);
    }
    if (tid < 128) {
        const long o = (long)blockIdx.x * NB * NODES + bz * NODES + m0 + tid;
        srcp[o] = s_r1[tid];
        dstp[o] = s_r2[tid];
    }
}

// ============================================================================
// GEMM2: att(fp16) @ Wh(hi/lo), 3-stage pipeline, 1 barrier/chunk.
// ============================================================================
#define G2_STAGE 49152
#define G2_SMEM  (3 * G2_STAGE)
__global__ __launch_bounds__(256) void gemm2_kernel(
    const __half* __restrict__ att,
    const __half* __restrict__ Bh, const __half* __restrict__ Bl,
    float* __restrict__ outp)
{
    extern __shared__ __align__(16) char smem[];
    const uint32_t sb = smem_u32(smem);
    const int tid  = threadIdx.x;
    const int lane = tid & 31;
    const int wid  = tid >> 5;
    const int wm   = wid >> 1;
    const int wn   = wid & 1;
    const int bz   = blockIdx.z;
    const int m0   = blockIdx.y * 128;
    const int n0   = blockIdx.x * 128;

    const __half* Ab  = att + (long)bz * NODES * NODES + (long)m0 * NODES;
    const __half* Bbh = Bh + (long)bz * NODES * FDIM + n0;
    const __half* Bbl = Bl + (long)bz * NODES * FDIM + n0;

    constexpr int NC = NODES / 64;

    float acc[2][8][4];
    #pragma unroll
    for (int i = 0; i < 2; i++)
        #pragma unroll
        for (int j = 0; j < 8; j++)
            #pragma unroll
            for (int q = 0; q < 4; q++) acc[i][j][q] = 0.f;

    auto load_chunk = [&](int st, int c) {
        const int k0 = c * 64;
        const uint32_t dA  = sb + st * G2_STAGE;
        const uint32_t dBh = dA + 16384;
        const uint32_t dBl = dA + 32768;
        #pragma unroll
        for (int i = 0; i < 4; i++) {
            int idx = tid + i * 256, r = idx >> 3, s = idx & 7;
            cp16(dA + SWZA(r * 128 + s * 16), Ab + (long)r * NODES + k0 + s * 8);
        }
        #pragma unroll
        for (int i = 0; i < 4; i++) {
            int idx = tid + i * 256, r = idx >> 4, s = idx & 15;
            cp16(dBh + SWZB(r * 256 + s * 16), Bbh + (long)(k0 + r) * FDIM + s * 8);
        }
        #pragma unroll
        for (int i = 0; i < 4; i++) {
            int idx = tid + i * 256, r = idx >> 4, s = idx & 15;
            cp16(dBl + SWZB(r * 256 + s * 16), Bbl + (long)(k0 + r) * FDIM + s * 8);
        }
        CP_COMMIT();
    };

    const int alr = lane & 15;
    const int alc = lane >> 4;

    load_chunk(0, 0);
    load_chunk(1, 1);
    for (int c = 0; c < NC; ++c) {
        if (c + 1 < NC) { CP_WAIT(1); } else { CP_WAIT(0); }
        __syncthreads();
        if (c + 2 < NC) load_chunk((c + 2) % 3, c + 2);

        const uint32_t sA = sb + (c % 3) * G2_STAGE;
        #pragma unroll
        for (int kk = 0; kk < 4; kk++) {
            uint32_t a[2][4];
            #pragma unroll
            for (int mt = 0; mt < 2; mt++)
                LDSM4(a[mt], sA + SWZA((wm * 32 + mt * 16 + alr) * 128 + kk * 32 + alc * 16));
            #pragma unroll
            for (int part = 0; part < 2; part++) {
                const uint32_t sB = sA + 16384 + part * 16384;
                uint32_t b[8][2];
                #pragma unroll
                for (int np = 0; np < 4; np++) {
                    uint32_t t0, t1, t2, t3;
                    LDSM4T(t0, t1, t2, t3,
                           sB + SWZB((kk * 16 + alr) * 256 + (wn * 64 + np * 16 + alc * 8) * 2));
                    b[2 * np][0] = t0; b[2 * np][1] = t1;
                    b[2 * np + 1][0] = t2; b[2 * np + 1][1] = t3;
                }
                #pragma unroll
                for (int mt = 0; mt < 2; mt++)
                    #pragma unroll
                    for (int nt = 0; nt < 8; nt++)
                        mma16816(acc[mt][nt], a[mt], b[nt]);
            }
        }
    }

    const int g  = lane >> 2;
    const int t2 = (lane & 3) * 2;
    #pragma unroll
    for (int mt = 0; mt < 2; mt++)
        #pragma unroll
        for (int nt = 0; nt < 8; nt++) {
            const long base = ((long)bz * NODES + m0 + wm * 32 + mt * 16) * FDIM
                            + n0 + wn * 64 + nt * 8 + t2;
            float v0 = acc[mt][nt][0], v1 = acc[mt][nt][1];
            float v2 = acc[mt][nt][2], v3 = acc[mt][nt][3];
            float2 r01, r23;
            r01.x = v0 > 0.f ? v0 : fast_exp(v0) - 1.f;
            r01.y = v1 > 0.f ? v1 : fast_exp(v1) - 1.f;
            r23.x = v2 > 0.f ? v2 : fast_exp(v2) - 1.f;
            r23.y = v3 > 0.f ? v3 : fast_exp(v3) - 1.f;
            *(float2*)(outp + base + (long)g * FDIM)       = r01;
            *(float2*)(outp + base + (long)(g + 8) * FDIM) = r23;
        }
}

// ============================================================================
// fp32 -> fp16 hi/lo split
// ============================================================================
__global__ __launch_bounds__(256) void conv_split(const float4* __restrict__ in4,
                                                  __half* __restrict__ hh,
                                                  __half* __restrict__ hl)
{
    long i = (long)blockIdx.x * 256 + threadIdx.x;
    float4 v = in4[i];
    __half2 h0, h1, l0, l1;
    h0.x = __float2half(v.x); h0.y = __float2half(v.y);
    h1.x = __float2half(v.z); h1.y = __float2half(v.w);
    l0.x = __float2half(v.x - __half2float(h0.x));
    l0.y = __float2half(v.y - __half2float(h0.y));
    l1.x = __float2half(v.z - __half2float(h1.x));
    l1.y = __float2half(v.w - __half2float(h1.y));
    ((__half2*)hh)[2 * i] = h0; ((__half2*)hh)[2 * i + 1] = h1;
    ((__half2*)hl)[2 * i] = l0; ((__half2*)hl)[2 * i + 1] = l1;
}

// ============================================================================
// Warp-per-row masked softmax, fully coalesced (q = k*32 + lane).
// ============================================================================
__global__ __launch_bounds__(256) void attn_kernel(const int* __restrict__ adj,
                                                   const float* __restrict__ srcp,
                                                   const float* __restrict__ dstp,
                                                   __half* __restrict__ att)
{
    const int warp = threadIdx.x >> 5;
    const int lane = threadIdx.x & 31;
    const int row  = blockIdx.x * 8 + warp;
    const int bn   = row >> 9;
    const int i    = row & (NODES - 1);

    const float si = srcp[bn * NODES + i] + srcp[NB * NODES + bn * NODES + i];
    const int4*   adj4 = (const int4*)(adj + i * NODES);
    const float4* d1v  = (const float4*)(dstp + bn * NODES);
    const float4* d2v  = (const float4*)(dstp + NB * NODES + bn * NODES);

    float p[16];
    float sum = 0.f;
    #pragma unroll
    for (int k = 0; k < 4; k++) {
        const int q = k * 32 + lane;              // coalesced vec4 index
        int4   av = adj4[q];
        float4 a1 = d1v[q];
        float4 a2 = d2v[q];
        float e0 = si + a1.x + a2.x; e0 = e0 > 0.f ? e0 : ALPHA * e0;
        float e1 = si + a1.y + a2.y; e1 = e1 > 0.f ? e1 : ALPHA * e1;
        float e2 = si + a1.z + a2.z; e2 = e2 > 0.f ? e2 : ALPHA * e2;
        float e3 = si + a1.w + a2.w; e3 = e3 > 0.f ? e3 : ALPHA * e3;
        p[k * 4 + 0] = (av.x > 0) ? fast_exp(e0) : 0.f;
        p[k * 4 + 1] = (av.y > 0) ? fast_exp(e1) : 0.f;
        p[k * 4 + 2] = (av.z > 0) ? fast_exp(e2) : 0.f;
        p[k * 4 + 3] = (av.w > 0) ? fast_exp(e3) : 0.f;
        sum += p[k * 4 + 0] + p[k * 4 + 1] + p[k * 4 + 2] + p[k * 4 + 3];
    }
    #pragma unroll
    for (int o = 16; o; o >>= 1) sum += __shfl_xor_sync(0xffffffffu, sum, o);
    const float rinv = __frcp_rn(sum);

    __half* arow = att + ((long)bn * NODES + i) * NODES;
    #pragma unroll
    for (int k = 0; k < 4; k++) {
        __half2 h2[2];
        h2[0].x = __float2half(p[k * 4 + 0] * rinv);
        h2[0].y = __float2half(p[k * 4 + 1] * rinv);
        h2[1].x = __float2half(p[k * 4 + 2] * rinv);
        h2[1].y = __float2half(p[k * 4 + 3] * rinv);
        *(uint2*)(arow + k * 128 + lane * 4) = *(uint2*)h2;   // coalesced 256B/warp
    }
}

// ============================================================================
extern "C" void kernel_launch(void* const* d_in, const int* in_sizes, int n_in,
                              void* d_out, int out_size)
{
    const float* h   = (const float*)d_in[0];
    const int*   adj = (const int*)d_in[1];
    const float* W   = (const float*)d_in[2];
    const float* a   = (const float*)d_in[3];
    float* out = (float*)d_out;

    __half *hh, *hl, *atp, *wh, *wl, *whh, *whl;
    float *srcp, *dstp;
    cudaGetSymbolAddress((void**)&hh,  g_h_hi);
    cudaGetSymbolAddress((void**)&hl,  g_h_lo);
    cudaGetSymbolAddress((void**)&atp, g_att);
    cudaGetSymbolAddress((void**)&wh,  g_W_hi);
    cudaGetSymbolAddress((void**)&wl,  g_W_lo);
    cudaGetSymbolAddress((void**)&whh, g_Wh_hi);
    cudaGetSymbolAddress((void**)&whl, g_Wh_lo);
    cudaGetSymbolAddress((void**)&srcp, g_srcp);
    cudaGetSymbolAddress((void**)&dstp, g_dstp);

    cudaFuncSetAttribute(gemm1_kernel, cudaFuncAttributeMaxDynamicSharedMemorySize, G1_SMEM);
    cudaFuncSetAttribute(gemm2_kernel, cudaFuncAttributeMaxDynamicSharedMemorySize, G2_SMEM);

    // 1) fp32 -> fp16 hi/lo
    conv_split<<<(NB * NODES * FDIM) / (4 * 256), 256>>>((const float4*)h, hh, hl);
    conv_split<<<(FDIM * FDIM) / (4 * 256), 256>>>((const float4*)W, wh, wl);

    // 2) GEMM1 (3-pass fp16) + fused src/dst epilogue
    {
        dim3 grid(FDIM / 128, NODES / 128, NB);
        gemm1_kernel<<<grid, 256, G1_SMEM>>>(hh, hl, wh, wl, whh, whl, srcp, dstp, a);
    }

    // 3) masked softmax -> att fp16 (warp per row, coalesced)
    attn_kernel<<<NB * NODES / 8, 256>>>(adj, srcp, dstp, atp);

    // 4) GEMM2 (2-part fp16) + ELU
    {
        dim3 grid(FDIM / 128, NODES / 128, NB);
        gemm2_kernel<<<grid, 256, G2_SMEM>>>(atp, whh, whl, out);
    }
}

// round 8
// speedup vs baseline: 4.7906x; 1.6608x over previous
#include <cuda_runtime.h>
#include <cuda_fp16.h>
#include <cstdint>
#include <math.h>

#define NB    64
#define NODES 512
#define FDIM  256
#define ALPHA 0.2f

// ---------------- scratch ----------------
__device__ __half g_h16 [NB * NODES * FDIM];
__device__ __half g_att [NB * NODES * NODES];
__device__ __half g_Wh  [NB * NODES * FDIM];
__device__ __half g_W16 [FDIM * FDIM];
__device__ float  g_wa  [2 * FDIM];
__device__ float  g_src [NB * NODES];
__device__ float  g_dst [NB * NODES];

// ---------------- helpers ----------------
__device__ __forceinline__ uint32_t smem_u32(const void* p) {
    uint32_t a;
    asm("{ .reg .u64 t; cvta.to.shared.u64 t, %1; cvt.u32.u64 %0, t; }" : "=r"(a) : "l"(p));
    return a;
}
__device__ __forceinline__ void cp16(uint32_t d, const void* g) {
    asm volatile("cp.async.cg.shared.global [%0], [%1], 16;" :: "r"(d), "l"(g));
}
#define CP_COMMIT() asm volatile("cp.async.commit_group;" ::: "memory")
#define CP_WAIT(n)  asm volatile("cp.async.wait_group %0;" :: "n"(n) : "memory")

#define LDSM4(r, addr)                                                       \
    asm volatile("ldmatrix.sync.aligned.m8n8.x4.shared.b16 {%0,%1,%2,%3}, [%4];" \
        : "=r"((r)[0]), "=r"((r)[1]), "=r"((r)[2]), "=r"((r)[3]) : "r"(addr))
#define LDSM4T(r0, r1, r2, r3, addr)                                         \
    asm volatile("ldmatrix.sync.aligned.m8n8.x4.trans.shared.b16 {%0,%1,%2,%3}, [%4];" \
        : "=r"(r0), "=r"(r1), "=r"(r2), "=r"(r3) : "r"(addr))

__device__ __forceinline__ void mma16816(float* d, const uint32_t* a, const uint32_t* b) {
    asm volatile(
        "mma.sync.aligned.m16n8k16.row.col.f32.f16.f16.f32 "
        "{%0,%1,%2,%3}, {%4,%5,%6,%7}, {%8,%9}, {%0,%1,%2,%3};"
        : "+f"(d[0]), "+f"(d[1]), "+f"(d[2]), "+f"(d[3])
        : "r"(a[0]), "r"(a[1]), "r"(a[2]), "r"(a[3]), "r"(b[0]), "r"(b[1]));
}

#define SWZA(x) ((x) ^ (((x) >> 3) & 0x70))
#define SWZB(x) ((x) ^ (((x) >> 4) & 0x70))

// degree-6 FMA-only exp (epilogue ELU)
__device__ __forceinline__ float fast_exp(float x) {
    x = fmaxf(x, -80.0f);
    float n = rintf(x * 1.442695041f);
    float r = fmaf(n, -0.693359375f, x);
    r = fmaf(n, 2.12194440e-4f, r);
    float p = 1.9875691500E-4f;
    p = fmaf(p, r, 1.3981999507E-3f);
    p = fmaf(p, r, 8.3334519073E-3f);
    p = fmaf(p, r, 4.1665795894E-2f);
    p = fmaf(p, r, 1.6666665459E-1f);
    p = fmaf(p, r, 5.0000001201E-1f);
    float z = fmaf(p * r, r, r) + 1.0f;
    return z * __int_as_float(((int)n + 127) << 23);
}
// degree-5 (softmax weights; fp16-level accuracy is plenty)
__device__ __forceinline__ float fast_exp5(float x) {
    x = fmaxf(x, -80.0f);
    float n = rintf(x * 1.442695041f);
    float r = fmaf(n, -0.693359375f, x);
    r = fmaf(n, 2.12194440e-4f, r);
    float p = 8.3333333e-3f;
    p = fmaf(p, r, 4.1666667e-2f);
    p = fmaf(p, r, 1.6666667e-1f);
    p = fmaf(p, r, 0.5f);
    p = fmaf(p, r, 1.0f);
    p = fmaf(p, r, 1.0f);
    return p * __int_as_float(((int)n + 127) << 23);
}

// ============================================================================
// prep_w: W fp32 -> fp16, plus wa1 = W @ a1, wa2 = W @ a2 (fp32, exact-ish).
// grid 64 x 256.
// ============================================================================
__global__ __launch_bounds__(256) void prep_w(const float* __restrict__ W,
                                              const float* __restrict__ a,
                                              __half* __restrict__ W16,
                                              float* __restrict__ wa)
{
    const int b = blockIdx.x, tid = threadIdx.x;
    // convert 4 floats
    {
        long i = (long)b * 256 + tid;           // float4 index, 16384 total
        float4 v = ((const float4*)W)[i];
        __half2 h0, h1;
        h0.x = __float2half(v.x); h0.y = __float2half(v.y);
        h1.x = __float2half(v.z); h1.y = __float2half(v.w);
        ((__half2*)W16)[2 * i] = h0; ((__half2*)W16)[2 * i + 1] = h1;
    }
    // wa dots: blocks 0..31, warp per k-row
    if (b < 32) {
        const int w = tid >> 5, lane = tid & 31;
        const int k = b * 8 + w;                 // 0..255
        const float* row = W + (long)k * FDIM;
        float s1 = 0.f, s2 = 0.f;
        #pragma unroll
        for (int f = lane; f < FDIM; f += 32) {
            float v = row[f];
            s1 = fmaf(v, a[f], s1);
            s2 = fmaf(v, a[FDIM + f], s2);
        }
        #pragma unroll
        for (int o = 16; o; o >>= 1) {
            s1 += __shfl_xor_sync(0xffffffffu, s1, o);
            s2 += __shfl_xor_sync(0xffffffffu, s2, o);
        }
        if (lane == 0) { wa[k] = s1; wa[FDIM + k] = s2; }
    }
}

// ============================================================================
// conv_h: h fp32 -> fp16, fused exact src/dst = h . wa1 / h . wa2.
// warp per node row; grid 4096 x 256.
// ============================================================================
__global__ __launch_bounds__(256) void conv_h(const float4* __restrict__ h4,
                                              __half* __restrict__ hh,
                                              const float* __restrict__ wa,
                                              float* __restrict__ srcv,
                                              float* __restrict__ dstv)
{
    const int warp = threadIdx.x >> 5;
    const int lane = threadIdx.x & 31;
    const long row = (long)blockIdx.x * 8 + warp;      // 0..32767
    const float4* hrow = h4 + row * 64;

    float4 v0 = hrow[2 * lane];
    float4 v1 = hrow[2 * lane + 1];

    // convert + store
    __half2 o[4];
    o[0].x = __float2half(v0.x); o[0].y = __float2half(v0.y);
    o[1].x = __float2half(v0.z); o[1].y = __float2half(v0.w);
    o[2].x = __float2half(v1.x); o[2].y = __float2half(v1.y);
    o[3].x = __float2half(v1.z); o[3].y = __float2half(v1.w);
    *(uint4*)(hh + row * FDIM + lane * 8) = *(uint4*)o;

    // dots (f = lane*8 + i)
    const float4* w14 = (const float4*)(wa) + lane * 2;
    const float4* w24 = (const float4*)(wa + FDIM) + lane * 2;
    float4 a0 = w14[0], a1v = w14[1], b0 = w24[0], b1 = w24[1];
    float s1 = v0.x * a0.x + v0.y * a0.y + v0.z * a0.z + v0.w * a0.w
             + v1.x * a1v.x + v1.y * a1v.y + v1.z * a1v.z + v1.w * a1v.w;
    float s2 = v0.x * b0.x + v0.y * b0.y + v0.z * b0.z + v0.w * b0.w
             + v1.x * b1.x + v1.y * b1.y + v1.z * b1.z + v1.w * b1.w;
    #pragma unroll
    for (int o2 = 16; o2; o2 >>= 1) {
        s1 += __shfl_xor_sync(0xffffffffu, s1, o2);
        s2 += __shfl_xor_sync(0xffffffffu, s2, o2);
    }
    if (lane == 0) { srcv[row] = s1; dstv[row] = s2; }
}

// ============================================================================
// GEMM1: Wh = h16 @ W16, single-pass fp16, fp32 acc, 3-stage pipeline.
// ============================================================================
#define G1_STAGE 32768
#define G1_SMEM  (3 * G1_STAGE)
__global__ __launch_bounds__(256) void gemm1_kernel(
    const __half* __restrict__ A, const __half* __restrict__ B,
    __half* __restrict__ Wh)
{
    extern __shared__ __align__(16) char smem[];
    const uint32_t sb = smem_u32(smem);
    const int tid  = threadIdx.x;
    const int lane = tid & 31;
    const int wid  = tid >> 5;
    const int wm   = wid >> 1;
    const int wn   = wid & 1;
    const int bz   = blockIdx.z;
    const int m0   = blockIdx.y * 128;
    const int n0   = blockIdx.x * 128;

    const __half* Ab = A + (long)bz * NODES * FDIM + (long)m0 * FDIM;
    const __half* Bb = B + n0;

    constexpr int NC = FDIM / 64;   // 4

    float acc[2][8][4];
    #pragma unroll
    for (int i = 0; i < 2; i++)
        #pragma unroll
        for (int j = 0; j < 8; j++)
            #pragma unroll
            for (int q = 0; q < 4; q++) acc[i][j][q] = 0.f;

    auto load_chunk = [&](int st, int c) {
        const int k0 = c * 64;
        const uint32_t dA = sb + st * G1_STAGE;
        const uint32_t dB = dA + 16384;
        #pragma unroll
        for (int i = 0; i < 4; i++) {
            int idx = tid + i * 256, r = idx >> 3, s = idx & 7;
            cp16(dA + SWZA(r * 128 + s * 16), Ab + (long)r * FDIM + k0 + s * 8);
        }
        #pragma unroll
        for (int i = 0; i < 4; i++) {
            int idx = tid + i * 256, r = idx >> 4, s = idx & 15;
            cp16(dB + SWZB(r * 256 + s * 16), Bb + (long)(k0 + r) * FDIM + s * 8);
        }
        CP_COMMIT();
    };

    const int alr = lane & 15;
    const int alc = lane >> 4;

    load_chunk(0, 0);
    load_chunk(1, 1);
    for (int c = 0; c < NC; ++c) {
        if (c + 1 < NC) { CP_WAIT(1); } else { CP_WAIT(0); }
        __syncthreads();
        if (c + 2 < NC) load_chunk((c + 2) % 3, c + 2);

        const uint32_t sA = sb + (c % 3) * G1_STAGE;
        const uint32_t sB = sA + 16384;
        #pragma unroll
        for (int kk = 0; kk < 4; kk++) {
            uint32_t a[2][4];
            #pragma unroll
            for (int mt = 0; mt < 2; mt++)
                LDSM4(a[mt], sA + SWZA((wm * 32 + mt * 16 + alr) * 128 + kk * 32 + alc * 16));
            uint32_t b[8][2];
            #pragma unroll
            for (int np = 0; np < 4; np++) {
                uint32_t t0, t1, t2, t3;
                LDSM4T(t0, t1, t2, t3,
                       sB + SWZB((kk * 16 + alr) * 256 + (wn * 64 + np * 16 + alc * 8) * 2));
                b[2 * np][0] = t0; b[2 * np][1] = t1;
                b[2 * np + 1][0] = t2; b[2 * np + 1][1] = t3;
            }
            #pragma unroll
            for (int mt = 0; mt < 2; mt++)
                #pragma unroll
                for (int nt = 0; nt < 8; nt++)
                    mma16816(acc[mt][nt], a[mt], b[nt]);
        }
    }

    __syncthreads();
    const int g  = lane >> 2;
    const int t2 = (lane & 3) * 2;
    __half2* cT = (__half2*)(smem);
    #pragma unroll
    for (int mt = 0; mt < 2; mt++)
        #pragma unroll
        for (int nt = 0; nt < 8; nt++) {
            const int r  = wm * 32 + mt * 16 + g;
            const int cc = wn * 64 + nt * 8 + t2;
            __half2 h01, h23;
            h01.x = __float2half(acc[mt][nt][0]); h01.y = __float2half(acc[mt][nt][1]);
            h23.x = __float2half(acc[mt][nt][2]); h23.y = __float2half(acc[mt][nt][3]);
            cT[(r * 128 + cc) >> 1]       = h01;
            cT[((r + 8) * 128 + cc) >> 1] = h23;
        }
    __syncthreads();
    #pragma unroll
    for (int i = 0; i < 8; i++) {
        int idx = tid + i * 256;           // 2048 uint4s
        int r = idx >> 4, ch = idx & 15;
        long gofs = ((long)bz * NODES + m0 + r) * FDIM + n0 + ch * 8;
        *(uint4*)(Wh + gofs) = *(uint4*)(smem + r * 256 + ch * 16);
    }
}

// ============================================================================
// GEMM2: out = elu(att @ Wh), single fp16 B, 3-stage pipeline.
// ============================================================================
#define G2_STAGE 32768
#define G2_SMEM  (3 * G2_STAGE)
__global__ __launch_bounds__(256) void gemm2_kernel(
    const __half* __restrict__ att, const __half* __restrict__ B,
    float* __restrict__ outp)
{
    extern __shared__ __align__(16) char smem[];
    const uint32_t sb = smem_u32(smem);
    const int tid  = threadIdx.x;
    const int lane = tid & 31;
    const int wid  = tid >> 5;
    const int wm   = wid >> 1;
    const int wn   = wid & 1;
    const int bz   = blockIdx.z;
    const int m0   = blockIdx.y * 128;
    const int n0   = blockIdx.x * 128;

    const __half* Ab = att + (long)bz * NODES * NODES + (long)m0 * NODES;
    const __half* Bb = B + (long)bz * NODES * FDIM + n0;

    constexpr int NC = NODES / 64;   // 8

    float acc[2][8][4];
    #pragma unroll
    for (int i = 0; i < 2; i++)
        #pragma unroll
        for (int j = 0; j < 8; j++)
            #pragma unroll
            for (int q = 0; q < 4; q++) acc[i][j][q] = 0.f;

    auto load_chunk = [&](int st, int c) {
        const int k0 = c * 64;
        const uint32_t dA = sb + st * G2_STAGE;
        const uint32_t dB = dA + 16384;
        #pragma unroll
        for (int i = 0; i < 4; i++) {
            int idx = tid + i * 256, r = idx >> 3, s = idx & 7;
            cp16(dA + SWZA(r * 128 + s * 16), Ab + (long)r * NODES + k0 + s * 8);
        }
        #pragma unroll
        for (int i = 0; i < 4; i++) {
            int idx = tid + i * 256, r = idx >> 4, s = idx & 15;
            cp16(dB + SWZB(r * 256 + s * 16), Bb + (long)(k0 + r) * FDIM + s * 8);
        }
        CP_COMMIT();
    };

    const int alr = lane & 15;
    const int alc = lane >> 4;

    load_chunk(0, 0);
    load_chunk(1, 1);
    for (int c = 0; c < NC; ++c) {
        if (c + 1 < NC) { CP_WAIT(1); } else { CP_WAIT(0); }
        __syncthreads();
        if (c + 2 < NC) load_chunk((c + 2) % 3, c + 2);

        const uint32_t sA = sb + (c % 3) * G2_STAGE;
        const uint32_t sB = sA + 16384;
        #pragma unroll
        for (int kk = 0; kk < 4; kk++) {
            uint32_t a[2][4];
            #pragma unroll
            for (int mt = 0; mt < 2; mt++)
                LDSM4(a[mt], sA + SWZA((wm * 32 + mt * 16 + alr) * 128 + kk * 32 + alc * 16));
            uint32_t b[8][2];
            #pragma unroll
            for (int np = 0; np < 4; np++) {
                uint32_t t0, t1, t2, t3;
                LDSM4T(t0, t1, t2, t3,
                       sB + SWZB((kk * 16 + alr) * 256 + (wn * 64 + np * 16 + alc * 8) * 2));
                b[2 * np][0] = t0; b[2 * np][1] = t1;
                b[2 * np + 1][0] = t2; b[2 * np + 1][1] = t3;
            }
            #pragma unroll
            for (int mt = 0; mt < 2; mt++)
                #pragma unroll
                for (int nt = 0; nt < 8; nt++)
                    mma16816(acc[mt][nt], a[mt], b[nt]);
        }
    }

    const int g  = lane >> 2;
    const int t2 = (lane & 3) * 2;
    #pragma unroll
    for (int mt = 0; mt < 2; mt++)
        #pragma unroll
        for (int nt = 0; nt < 8; nt++) {
            const long base = ((long)bz * NODES + m0 + wm * 32 + mt * 16) * FDIM
                            + n0 + wn * 64 + nt * 8 + t2;
            float v0 = acc[mt][nt][0], v1 = acc[mt][nt][1];
            float v2 = acc[mt][nt][2], v3 = acc[mt][nt][3];
            float2 r01, r23;
            r01.x = v0 > 0.f ? v0 : fast_exp(v0) - 1.f;
            r01.y = v1 > 0.f ? v1 : fast_exp(v1) - 1.f;
            r23.x = v2 > 0.f ? v2 : fast_exp(v2) - 1.f;
            r23.y = v3 > 0.f ? v3 : fast_exp(v3) - 1.f;
            *(float2*)(outp + base + (long)g * FDIM)       = r01;
            *(float2*)(outp + base + (long)(g + 8) * FDIM) = r23;
        }
}

// ============================================================================
// Warp-per-row masked softmax (coalesced), single src/dst arrays.
// ============================================================================
__global__ __launch_bounds__(256) void attn_kernel(const int* __restrict__ adj,
                                                   const float* __restrict__ srcv,
                                                   const float* __restrict__ dstv,
                                                   __half* __restrict__ att)
{
    const int warp = threadIdx.x >> 5;
    const int lane = threadIdx.x & 31;
    const int row  = blockIdx.x * 8 + warp;
    const int bn   = row >> 9;
    const int i    = row & (NODES - 1);

    const float si = srcv[row];
    const int4*   adj4 = (const int4*)(adj + i * NODES);
    const float4* dv   = (const float4*)(dstv + bn * NODES);

    float p[16];
    float sum = 0.f;
    #pragma unroll
    for (int k = 0; k < 4; k++) {
        const int q = k * 32 + lane;
        int4   av = adj4[q];
        float4 d  = dv[q];
        float e0 = si + d.x; e0 = e0 > 0.f ? e0 : ALPHA * e0;
        float e1 = si + d.y; e1 = e1 > 0.f ? e1 : ALPHA * e1;
        float e2 = si + d.z; e2 = e2 > 0.f ? e2 : ALPHA * e2;
        float e3 = si + d.w; e3 = e3 > 0.f ? e3 : ALPHA * e3;
        p[k * 4 + 0] = (av.x > 0) ? fast_exp5(e0) : 0.f;
        p[k * 4 + 1] = (av.y > 0) ? fast_exp5(e1) : 0.f;
        p[k * 4 + 2] = (av.z > 0) ? fast_exp5(e2) : 0.f;
        p[k * 4 + 3] = (av.w > 0) ? fast_exp5(e3) : 0.f;
        sum += p[k * 4 + 0] + p[k * 4 + 1] + p[k * 4 + 2] + p[k * 4 + 3];
    }
    #pragma unroll
    for (int o = 16; o; o >>= 1) sum += __shfl_xor_sync(0xffffffffu, sum, o);
    const float rinv = __frcp_rn(sum);

    __half* arow = att + ((long)bn * NODES + i) * NODES;
    #pragma unroll
    for (int k = 0; k < 4; k++) {
        __half2 h2[2];
        h2[0].x = __float2half(p[k * 4 + 0] * rinv);
        h2[0].y = __float2half(p[k * 4 + 1] * rinv);
        h2[1].x = __float2half(p[k * 4 + 2] * rinv);
        h2[1].y = __float2half(p[k * 4 + 3] * rinv);
        *(uint2*)(arow + k * 128 + lane * 4) = *(uint2*)h2;
    }
}

// ============================================================================
extern "C" void kernel_launch(void* const* d_in, const int* in_sizes, int n_in,
                              void* d_out, int out_size)
{
    const float* h   = (const float*)d_in[0];
    const int*   adj = (const int*)d_in[1];
    const float* W   = (const float*)d_in[2];
    const float* a   = (const float*)d_in[3];
    float* out = (float*)d_out;

    __half *hh, *atp, *w16, *wh;
    float *wa, *srcp, *dstp;
    cudaGetSymbolAddress((void**)&hh,  g_h16);
    cudaGetSymbolAddress((void**)&atp, g_att);
    cudaGetSymbolAddress((void**)&w16, g_W16);
    cudaGetSymbolAddress((void**)&wh,  g_Wh);
    cudaGetSymbolAddress((void**)&wa,  g_wa);
    cudaGetSymbolAddress((void**)&srcp, g_src);
    cudaGetSymbolAddress((void**)&dstp, g_dst);

    cudaFuncSetAttribute(gemm1_kernel, cudaFuncAttributeMaxDynamicSharedMemorySize, G1_SMEM);
    cudaFuncSetAttribute(gemm2_kernel, cudaFuncAttributeMaxDynamicSharedMemorySize, G2_SMEM);

    // 1) W fp16 + wa projections
    prep_w<<<64, 256>>>(W, a, w16, wa);

    // 2) h fp16 + exact fp32 src/dst (associativity trick)
    conv_h<<<NB * NODES / 8, 256>>>((const float4*)h, hh, wa, srcp, dstp);

    // 3) masked softmax -> att fp16
    attn_kernel<<<NB * NODES / 8, 256>>>(adj, srcp, dstp, atp);

    // 4) GEMM1: Wh = h @ W (1-pass fp16)
    {
        dim3 grid(FDIM / 128, NODES / 128, NB);
        gemm1_kernel<<<grid, 256, G1_SMEM>>>(hh, w16, wh);
    }

    // 5) GEMM2: out = elu(att @ Wh) (1-pass fp16)
    {
        dim3 grid(FDIM / 128, NODES / 128, NB);
        gemm2_kernel<<<grid, 256, G2_SMEM>>>(atp, wh, out);
    }
}

// round 9
// speedup vs baseline: 5.0516x; 1.0545x over previous
#include <cuda_runtime.h>
#include <cuda_fp16.h>
#include <cstdint>
#include <math.h>

#define NB    64
#define NODES 512
#define FDIM  256
#define ALPHA 0.2f

// ---------------- scratch ----------------
__device__ __half g_h16 [NB * NODES * FDIM];
__device__ __half g_att [NB * NODES * NODES];
__device__ __half g_Wh  [NB * NODES * FDIM];
__device__ __half g_W16 [FDIM * FDIM];
__device__ float  g_wa  [2 * FDIM];
__device__ float  g_src [NB * NODES];
__device__ float  g_dst [NB * NODES];

// ---------------- helpers ----------------
__device__ __forceinline__ uint32_t smem_u32(const void* p) {
    uint32_t a;
    asm("{ .reg .u64 t; cvta.to.shared.u64 t, %1; cvt.u32.u64 %0, t; }" : "=r"(a) : "l"(p));
    return a;
}
__device__ __forceinline__ void cp16(uint32_t d, const void* g) {
    asm volatile("cp.async.cg.shared.global [%0], [%1], 16;" :: "r"(d), "l"(g));
}
#define CP_COMMIT() asm volatile("cp.async.commit_group;" ::: "memory")
#define CP_WAIT(n)  asm volatile("cp.async.wait_group %0;" :: "n"(n) : "memory")

#define LDSM4(r, addr)                                                       \
    asm volatile("ldmatrix.sync.aligned.m8n8.x4.shared.b16 {%0,%1,%2,%3}, [%4];" \
        : "=r"((r)[0]), "=r"((r)[1]), "=r"((r)[2]), "=r"((r)[3]) : "r"(addr))
#define LDSM4T(r0, r1, r2, r3, addr)                                         \
    asm volatile("ldmatrix.sync.aligned.m8n8.x4.trans.shared.b16 {%0,%1,%2,%3}, [%4];" \
        : "=r"(r0), "=r"(r1), "=r"(r2), "=r"(r3) : "r"(addr))

__device__ __forceinline__ void mma16816(float* d, const uint32_t* a, const uint32_t* b) {
    asm volatile(
        "mma.sync.aligned.m16n8k16.row.col.f32.f16.f16.f32 "
        "{%0,%1,%2,%3}, {%4,%5,%6,%7}, {%8,%9}, {%0,%1,%2,%3};"
        : "+f"(d[0]), "+f"(d[1]), "+f"(d[2]), "+f"(d[3])
        : "r"(a[0]), "r"(a[1]), "r"(a[2]), "r"(a[3]), "r"(b[0]), "r"(b[1]));
}

#define SWZA(x) ((x) ^ (((x) >> 3) & 0x70))
#define SWZB(x) ((x) ^ (((x) >> 4) & 0x70))

// degree-6 FMA-only exp (epilogue ELU)
__device__ __forceinline__ float fast_exp(float x) {
    x = fmaxf(x, -80.0f);
    float n = rintf(x * 1.442695041f);
    float r = fmaf(n, -0.693359375f, x);
    r = fmaf(n, 2.12194440e-4f, r);
    float p = 1.9875691500E-4f;
    p = fmaf(p, r, 1.3981999507E-3f);
    p = fmaf(p, r, 8.3334519073E-3f);
    p = fmaf(p, r, 4.1665795894E-2f);
    p = fmaf(p, r, 1.6666665459E-1f);
    p = fmaf(p, r, 5.0000001201E-1f);
    float z = fmaf(p * r, r, r) + 1.0f;
    return z * __int_as_float(((int)n + 127) << 23);
}
// degree-5 (softmax weights)
__device__ __forceinline__ float fast_exp5(float x) {
    x = fmaxf(x, -80.0f);
    float n = rintf(x * 1.442695041f);
    float r = fmaf(n, -0.693359375f, x);
    r = fmaf(n, 2.12194440e-4f, r);
    float p = 8.3333333e-3f;
    p = fmaf(p, r, 4.1666667e-2f);
    p = fmaf(p, r, 1.6666667e-1f);
    p = fmaf(p, r, 0.5f);
    p = fmaf(p, r, 1.0f);
    p = fmaf(p, r, 1.0f);
    return p * __int_as_float(((int)n + 127) << 23);
}

// ============================================================================
// prep_w: W fp32 -> fp16 + wa1/wa2 projections.
// ============================================================================
__global__ __launch_bounds__(256) void prep_w(const float* __restrict__ W,
                                              const float* __restrict__ a,
                                              __half* __restrict__ W16,
                                              float* __restrict__ wa)
{
    const int b = blockIdx.x, tid = threadIdx.x;
    {
        long i = (long)b * 256 + tid;
        float4 v = ((const float4*)W)[i];
        __half2 h0, h1;
        h0.x = __float2half(v.x); h0.y = __float2half(v.y);
        h1.x = __float2half(v.z); h1.y = __float2half(v.w);
        ((__half2*)W16)[2 * i] = h0; ((__half2*)W16)[2 * i + 1] = h1;
    }
    if (b < 32) {
        const int w = tid >> 5, lane = tid & 31;
        const int k = b * 8 + w;
        const float* row = W + (long)k * FDIM;
        float s1 = 0.f, s2 = 0.f;
        #pragma unroll
        for (int f = lane; f < FDIM; f += 32) {
            float v = row[f];
            s1 = fmaf(v, a[f], s1);
            s2 = fmaf(v, a[FDIM + f], s2);
        }
        #pragma unroll
        for (int o = 16; o; o >>= 1) {
            s1 += __shfl_xor_sync(0xffffffffu, s1, o);
            s2 += __shfl_xor_sync(0xffffffffu, s2, o);
        }
        if (lane == 0) { wa[k] = s1; wa[FDIM + k] = s2; }
    }
}

// ============================================================================
// conv_h: h fp32 -> fp16 + exact fp32 src/dst dots (associativity trick).
// ============================================================================
__global__ __launch_bounds__(256) void conv_h(const float4* __restrict__ h4,
                                              __half* __restrict__ hh,
                                              const float* __restrict__ wa,
                                              float* __restrict__ srcv,
                                              float* __restrict__ dstv)
{
    const int warp = threadIdx.x >> 5;
    const int lane = threadIdx.x & 31;
    const long row = (long)blockIdx.x * 8 + warp;
    const float4* hrow = h4 + row * 64;

    float4 v0 = hrow[2 * lane];
    float4 v1 = hrow[2 * lane + 1];

    __half2 o[4];
    o[0].x = __float2half(v0.x); o[0].y = __float2half(v0.y);
    o[1].x = __float2half(v0.z); o[1].y = __float2half(v0.w);
    o[2].x = __float2half(v1.x); o[2].y = __float2half(v1.y);
    o[3].x = __float2half(v1.z); o[3].y = __float2half(v1.w);
    *(uint4*)(hh + row * FDIM + lane * 8) = *(uint4*)o;

    const float4* w14 = (const float4*)(wa) + lane * 2;
    const float4* w24 = (const float4*)(wa + FDIM) + lane * 2;
    float4 a0 = w14[0], a1v = w14[1], b0 = w24[0], b1 = w24[1];
    float s1 = v0.x * a0.x + v0.y * a0.y + v0.z * a0.z + v0.w * a0.w
             + v1.x * a1v.x + v1.y * a1v.y + v1.z * a1v.z + v1.w * a1v.w;
    float s2 = v0.x * b0.x + v0.y * b0.y + v0.z * b0.z + v0.w * b0.w
             + v1.x * b1.x + v1.y * b1.y + v1.z * b1.z + v1.w * b1.w;
    #pragma unroll
    for (int o2 = 16; o2; o2 >>= 1) {
        s1 += __shfl_xor_sync(0xffffffffu, s1, o2);
        s2 += __shfl_xor_sync(0xffffffffu, s2, o2);
    }
    if (lane == 0) { srcv[row] = s1; dstv[row] = s2; }
}

// ============================================================================
// GEMM1: Wh = h16 @ W16, 1-pass fp16, 2-stage pipeline, 2 CTAs/SM.
// ============================================================================
#define G_STAGE 32768
#define G_SMEM  (2 * G_STAGE)
__global__ __launch_bounds__(256, 2) void gemm1_kernel(
    const __half* __restrict__ A, const __half* __restrict__ B,
    __half* __restrict__ Wh)
{
    extern __shared__ __align__(16) char smem[];
    const uint32_t sb = smem_u32(smem);
    const int tid  = threadIdx.x;
    const int lane = tid & 31;
    const int wid  = tid >> 5;
    const int wm   = wid >> 1;
    const int wn   = wid & 1;
    const int bz   = blockIdx.z;
    const int m0   = blockIdx.y * 128;
    const int n0   = blockIdx.x * 128;

    const __half* Ab = A + (long)bz * NODES * FDIM + (long)m0 * FDIM;
    const __half* Bb = B + n0;

    constexpr int NC = FDIM / 64;   // 4

    float acc[2][8][4];
    #pragma unroll
    for (int i = 0; i < 2; i++)
        #pragma unroll
        for (int j = 0; j < 8; j++)
            #pragma unroll
            for (int q = 0; q < 4; q++) acc[i][j][q] = 0.f;

    auto load_chunk = [&](int st, int c) {
        const int k0 = c * 64;
        const uint32_t dA = sb + st * G_STAGE;
        const uint32_t dB = dA + 16384;
        #pragma unroll
        for (int i = 0; i < 4; i++) {
            int idx = tid + i * 256, r = idx >> 3, s = idx & 7;
            cp16(dA + SWZA(r * 128 + s * 16), Ab + (long)r * FDIM + k0 + s * 8);
        }
        #pragma unroll
        for (int i = 0; i < 4; i++) {
            int idx = tid + i * 256, r = idx >> 4, s = idx & 15;
            cp16(dB + SWZB(r * 256 + s * 16), Bb + (long)(k0 + r) * FDIM + s * 8);
        }
        CP_COMMIT();
    };

    const int alr = lane & 15;
    const int alc = lane >> 4;

    load_chunk(0, 0);
    for (int c = 0; c < NC; ++c) {
        const int s = c & 1;
        if (c + 1 < NC) { load_chunk(s ^ 1, c + 1); CP_WAIT(1); }
        else            { CP_WAIT(0); }
        __syncthreads();

        const uint32_t sA = sb + s * G_STAGE;
        const uint32_t sB = sA + 16384;
        #pragma unroll
        for (int kk = 0; kk < 4; kk++) {
            uint32_t a[2][4];
            #pragma unroll
            for (int mt = 0; mt < 2; mt++)
                LDSM4(a[mt], sA + SWZA((wm * 32 + mt * 16 + alr) * 128 + kk * 32 + alc * 16));
            uint32_t b[8][2];
            #pragma unroll
            for (int np = 0; np < 4; np++) {
                uint32_t t0, t1, t2, t3;
                LDSM4T(t0, t1, t2, t3,
                       sB + SWZB((kk * 16 + alr) * 256 + (wn * 64 + np * 16 + alc * 8) * 2));
                b[2 * np][0] = t0; b[2 * np][1] = t1;
                b[2 * np + 1][0] = t2; b[2 * np + 1][1] = t3;
            }
            #pragma unroll
            for (int mt = 0; mt < 2; mt++)
                #pragma unroll
                for (int nt = 0; nt < 8; nt++)
                    mma16816(acc[mt][nt], a[mt], b[nt]);
        }
        __syncthreads();
    }

    const int g  = lane >> 2;
    const int t2 = (lane & 3) * 2;
    __half2* cT = (__half2*)(smem);
    #pragma unroll
    for (int mt = 0; mt < 2; mt++)
        #pragma unroll
        for (int nt = 0; nt < 8; nt++) {
            const int r  = wm * 32 + mt * 16 + g;
            const int cc = wn * 64 + nt * 8 + t2;
            __half2 h01, h23;
            h01.x = __float2half(acc[mt][nt][0]); h01.y = __float2half(acc[mt][nt][1]);
            h23.x = __float2half(acc[mt][nt][2]); h23.y = __float2half(acc[mt][nt][3]);
            cT[(r * 128 + cc) >> 1]       = h01;
            cT[((r + 8) * 128 + cc) >> 1] = h23;
        }
    __syncthreads();
    #pragma unroll
    for (int i = 0; i < 8; i++) {
        int idx = tid + i * 256;
        int r = idx >> 4, ch = idx & 15;
        long gofs = ((long)bz * NODES + m0 + r) * FDIM + n0 + ch * 8;
        *(uint4*)(Wh + gofs) = *(uint4*)(smem + r * 256 + ch * 16);
    }
}

// ============================================================================
// GEMM2: out = elu(att @ Wh), 1-pass fp16, 2-stage pipeline, 2 CTAs/SM.
// ============================================================================
__global__ __launch_bounds__(256, 2) void gemm2_kernel(
    const __half* __restrict__ att, const __half* __restrict__ B,
    float* __restrict__ outp)
{
    extern __shared__ __align__(16) char smem[];
    const uint32_t sb = smem_u32(smem);
    const int tid  = threadIdx.x;
    const int lane = tid & 31;
    const int wid  = tid >> 5;
    const int wm   = wid >> 1;
    const int wn   = wid & 1;
    const int bz   = blockIdx.z;
    const int m0   = blockIdx.y * 128;
    const int n0   = blockIdx.x * 128;

    const __half* Ab = att + (long)bz * NODES * NODES + (long)m0 * NODES;
    const __half* Bb = B + (long)bz * NODES * FDIM + n0;

    constexpr int NC = NODES / 64;   // 8

    float acc[2][8][4];
    #pragma unroll
    for (int i = 0; i < 2; i++)
        #pragma unroll
        for (int j = 0; j < 8; j++)
            #pragma unroll
            for (int q = 0; q < 4; q++) acc[i][j][q] = 0.f;

    auto load_chunk = [&](int st, int c) {
        const int k0 = c * 64;
        const uint32_t dA = sb + st * G_STAGE;
        const uint32_t dB = dA + 16384;
        #pragma unroll
        for (int i = 0; i < 4; i++) {
            int idx = tid + i * 256, r = idx >> 3, s = idx & 7;
            cp16(dA + SWZA(r * 128 + s * 16), Ab + (long)r * NODES + k0 + s * 8);
        }
        #pragma unroll
        for (int i = 0; i < 4; i++) {
            int idx = tid + i * 256, r = idx >> 4, s = idx & 15;
            cp16(dB + SWZB(r * 256 + s * 16), Bb + (long)(k0 + r) * FDIM + s * 8);
        }
        CP_COMMIT();
    };

    const int alr = lane & 15;
    const int alc = lane >> 4;

    load_chunk(0, 0);
    for (int c = 0; c < NC; ++c) {
        const int s = c & 1;
        if (c + 1 < NC) { load_chunk(s ^ 1, c + 1); CP_WAIT(1); }
        else            { CP_WAIT(0); }
        __syncthreads();

        const uint32_t sA = sb + s * G_STAGE;
        const uint32_t sB = sA + 16384;
        #pragma unroll
        for (int kk = 0; kk < 4; kk++) {
            uint32_t a[2][4];
            #pragma unroll
            for (int mt = 0; mt < 2; mt++)
                LDSM4(a[mt], sA + SWZA((wm * 32 + mt * 16 + alr) * 128 + kk * 32 + alc * 16));
            uint32_t b[8][2];
            #pragma unroll
            for (int np = 0; np < 4; np++) {
                uint32_t t0, t1, t2, t3;
                LDSM4T(t0, t1, t2, t3,
                       sB + SWZB((kk * 16 + alr) * 256 + (wn * 64 + np * 16 + alc * 8) * 2));
                b[2 * np][0] = t0; b[2 * np][1] = t1;
                b[2 * np + 1][0] = t2; b[2 * np + 1][1] = t3;
            }
            #pragma unroll
            for (int mt = 0; mt < 2; mt++)
                #pragma unroll
                for (int nt = 0; nt < 8; nt++)
                    mma16816(acc[mt][nt], a[mt], b[nt]);
        }
        __syncthreads();
    }

    const int g  = lane >> 2;
    const int t2 = (lane & 3) * 2;
    #pragma unroll
    for (int mt = 0; mt < 2; mt++)
        #pragma unroll
        for (int nt = 0; nt < 8; nt++) {
            const long base = ((long)bz * NODES + m0 + wm * 32 + mt * 16) * FDIM
                            + n0 + wn * 64 + nt * 8 + t2;
            float v0 = acc[mt][nt][0], v1 = acc[mt][nt][1];
            float v2 = acc[mt][nt][2], v3 = acc[mt][nt][3];
            float2 r01, r23;
            r01.x = v0 > 0.f ? v0 : fast_exp(v0) - 1.f;
            r01.y = v1 > 0.f ? v1 : fast_exp(v1) - 1.f;
            r23.x = v2 > 0.f ? v2 : fast_exp(v2) - 1.f;
            r23.y = v3 > 0.f ? v3 : fast_exp(v3) - 1.f;
            *(float2*)(outp + base + (long)g * FDIM)       = r01;
            *(float2*)(outp + base + (long)(g + 8) * FDIM) = r23;
        }
}

// ============================================================================
// Warp-per-row masked softmax (coalesced).
// ============================================================================
__global__ __launch_bounds__(256) void attn_kernel(const int* __restrict__ adj,
                                                   const float* __restrict__ srcv,
                                                   const float* __restrict__ dstv,
                                                   __half* __restrict__ att)
{
    const int warp = threadIdx.x >> 5;
    const int lane = threadIdx.x & 31;
    const int row  = blockIdx.x * 8 + warp;
    const int bn   = row >> 9;
    const int i    = row & (NODES - 1);

    const float si = srcv[row];
    const int4*   adj4 = (const int4*)(adj + i * NODES);
    const float4* dv   = (const float4*)(dstv + bn * NODES);

    float p[16];
    float sum = 0.f;
    #pragma unroll
    for (int k = 0; k < 4; k++) {
        const int q = k * 32 + lane;
        int4   av = adj4[q];
        float4 d  = dv[q];
        float e0 = si + d.x; e0 = e0 > 0.f ? e0 : ALPHA * e0;
        float e1 = si + d.y; e1 = e1 > 0.f ? e1 : ALPHA * e1;
        float e2 = si + d.z; e2 = e2 > 0.f ? e2 : ALPHA * e2;
        float e3 = si + d.w; e3 = e3 > 0.f ? e3 : ALPHA * e3;
        p[k * 4 + 0] = (av.x > 0) ? fast_exp5(e0) : 0.f;
        p[k * 4 + 1] = (av.y > 0) ? fast_exp5(e1) : 0.f;
        p[k * 4 + 2] = (av.z > 0) ? fast_exp5(e2) : 0.f;
        p[k * 4 + 3] = (av.w > 0) ? fast_exp5(e3) : 0.f;
        sum += p[k * 4 + 0] + p[k * 4 + 1] + p[k * 4 + 2] + p[k * 4 + 3];
    }
    #pragma unroll
    for (int o = 16; o; o >>= 1) sum += __shfl_xor_sync(0xffffffffu, sum, o);
    const float rinv = __frcp_rn(sum);

    __half* arow = att + ((long)bn * NODES + i) * NODES;
    #pragma unroll
    for (int k = 0; k < 4; k++) {
        __half2 h2[2];
        h2[0].x = __float2half(p[k * 4 + 0] * rinv);
        h2[0].y = __float2half(p[k * 4 + 1] * rinv);
        h2[1].x = __float2half(p[k * 4 + 2] * rinv);
        h2[1].y = __float2half(p[k * 4 + 3] * rinv);
        *(uint2*)(arow + k * 128 + lane * 4) = *(uint2*)h2;
    }
}

// ============================================================================
extern "C" void kernel_launch(void* const* d_in, const int* in_sizes, int n_in,
                              void* d_out, int out_size)
{
    const float* h   = (const float*)d_in[0];
    const int*   adj = (const int*)d_in[1];
    const float* W   = (const float*)d_in[2];
    const float* a   = (const float*)d_in[3];
    float* out = (float*)d_out;

    __half *hh, *atp, *w16, *wh;
    float *wa, *srcp, *dstp;
    cudaGetSymbolAddress((void**)&hh,  g_h16);
    cudaGetSymbolAddress((void**)&atp, g_att);
    cudaGetSymbolAddress((void**)&w16, g_W16);
    cudaGetSymbolAddress((void**)&wh,  g_Wh);
    cudaGetSymbolAddress((void**)&wa,  g_wa);
    cudaGetSymbolAddress((void**)&srcp, g_src);
    cudaGetSymbolAddress((void**)&dstp, g_dst);

    cudaFuncSetAttribute(gemm1_kernel, cudaFuncAttributeMaxDynamicSharedMemorySize, G_SMEM);
    cudaFuncSetAttribute(gemm2_kernel, cudaFuncAttributeMaxDynamicSharedMemorySize, G_SMEM);

    // 1) W fp16 + wa projections
    prep_w<<<64, 256>>>(W, a, w16, wa);

    // 2) h fp16 + exact fp32 src/dst
    conv_h<<<NB * NODES / 8, 256>>>((const float4*)h, hh, wa, srcp, dstp);

    // 3) masked softmax -> att fp16
    attn_kernel<<<NB * NODES / 8, 256>>>(adj, srcp, dstp, atp);

    // 4) GEMM1: Wh = h @ W
    {
        dim3 grid(FDIM / 128, NODES / 128, NB);
        gemm1_kernel<<<grid, 256, G_SMEM>>>(hh, w16, wh);
    }

    // 5) GEMM2: out = elu(att @ Wh)
    {
        dim3 grid(FDIM / 128, NODES / 128, NB);
        gemm2_kernel<<<grid, 256, G_SMEM>>>(atp, wh, out);
    }
}